// round 5
// baseline (speedup 1.0000x reference)
#include <cuda_runtime.h>
#include <cuda_fp16.h>
#include <cstdint>

#define Bsz 512
#define Nn  98
#define DIM 512
#define NH  16
#define HD  32
#define Mrows (Bsz*Nn)          // 50176
#define QKV_N (3*DIM)           // 1536
#define SCALE 0.17677669529663687f
#define XELEMS ((size_t)Mrows*DIM)   // 25,690,112

#define KT 32
#define NSTAGE 3
#define TILE_B 10240            // 128 rows * 80 B
#define STAGE_B (3*TILE_B)      // 30720 (A_hi, B_hi, B_lo)
#define SMEM_GEMM (NSTAGE*STAGE_B)  // 92160

// ---------------- scratch (device globals; allocation-free rule) ------------
__device__ float g_q[(size_t)Bsz*NH*Nn*HD];
__device__ float g_k[(size_t)Bsz*NH*Nn*HD];
__device__ float g_v[(size_t)Bsz*NH*Nn*HD];
__device__ __half g_xh[XELEMS];           // x rounded to fp16
__device__ __half g_ah[XELEMS];           // attn output rounded to fp16
__device__ __half g_wqh[(size_t)QKV_N*DIM];
__device__ __half g_wql[(size_t)QKV_N*DIM];
__device__ __half g_wph[(size_t)DIM*DIM];
__device__ __half g_wpl[(size_t)DIM*DIM];
__device__ float g_bias_pre[NH*Nn*Nn];

// ---------------- helpers ----------------------------------------------------
__device__ __forceinline__ uint32_t smem_u32(const void* p) {
    uint32_t a;
    asm("{ .reg .u64 t; cvta.to.shared.u64 t, %1; cvt.u32.u64 %0, t; }"
        : "=r"(a) : "l"(p));
    return a;
}
__device__ __forceinline__ void cp16(uint32_t s, const void* g) {
    asm volatile("cp.async.cg.shared.global [%0], [%1], 16;" :: "r"(s), "l"(g));
}
__device__ __forceinline__ void ldsm4(uint32_t& r0, uint32_t& r1, uint32_t& r2,
                                      uint32_t& r3, uint32_t a) {
    asm volatile("ldmatrix.sync.aligned.m8n8.x4.shared.b16 {%0,%1,%2,%3}, [%4];"
                 : "=r"(r0), "=r"(r1), "=r"(r2), "=r"(r3) : "r"(a));
}
__device__ __forceinline__ void mma4(float* d, const uint32_t* a, const uint32_t* b) {
    asm volatile("mma.sync.aligned.m16n8k16.row.col.f32.f16.f16.f32 "
                 "{%0,%1,%2,%3}, {%4,%5,%6,%7}, {%8,%9}, {%0,%1,%2,%3};"
                 : "+f"(d[0]), "+f"(d[1]), "+f"(d[2]), "+f"(d[3])
                 : "r"(a[0]), "r"(a[1]), "r"(a[2]), "r"(a[3]), "r"(b[0]), "r"(b[1]));
}
__device__ __forceinline__ uint32_t packh2(__half a, __half b) {
    __half2 t = __halves2half2(a, b);
    return reinterpret_cast<uint32_t&>(t);
}

// ---------------- conversion kernels ----------------------------------------
__global__ __launch_bounds__(256) void conv_x_kernel(const float* __restrict__ x) {
    size_t i = (size_t)blockIdx.x * 256 + threadIdx.x;
    if (i >= XELEMS / 4) return;
    float4 v = ((const float4*)x)[i];
    ((uint2*)g_xh)[i] = make_uint2(
        packh2(__float2half(v.x), __float2half(v.y)),
        packh2(__float2half(v.z), __float2half(v.w)));
}
__global__ __launch_bounds__(256) void transw_qkv_kernel(const float* __restrict__ w) {
    int idx = blockIdx.x * 256 + threadIdx.x;
    if (idx >= QKV_N * DIM) return;
    int n = idx >> 9, k = idx & 511;
    float v = w[(size_t)k * QKV_N + n];
    __half h = __float2half(v);
    g_wqh[idx] = h;
    g_wql[idx] = __float2half(v - __half2float(h));
}
__global__ __launch_bounds__(256) void transw_proj_kernel(const float* __restrict__ w) {
    int idx = blockIdx.x * 256 + threadIdx.x;
    if (idx >= DIM * DIM) return;
    int n = idx >> 9, k = idx & 511;
    float v = w[(size_t)k * DIM + n];
    __half h = __float2half(v);
    g_wph[idx] = h;
    g_wpl[idx] = __float2half(v - __half2float(h));
}
__global__ __launch_bounds__(256) void bias_pre_kernel(const float* __restrict__ bt,
                                                       const int* __restrict__ ri) {
    int idx = blockIdx.x * 256 + threadIdx.x;
    if (idx >= NH * Nn * Nn) return;
    int h = idx / (Nn * Nn);
    int t = idx - h * (Nn * Nn);
    g_bias_pre[idx] = bt[ri[t] * NH + h];
}

// ---------------- HMMA GEMM: 128x128 tile, fp16, D = A_hi*(B_hi + B_lo) -----
// A: [M,512] fp16 row-major; B: [N,512] fp16 hi/lo (pre-transposed weights).
template<bool IS_QKV>
__global__ __launch_bounds__(256, 2) void gemm_kernel(const float* __restrict__ bias,
                                                      float* __restrict__ outp) {
    extern __shared__ __align__(16) char smraw[];
    const uint32_t sbase = smem_u32(smraw);
    const int tid = threadIdx.x;
    const int wid = tid >> 5, l = tid & 31;
    const int bm = blockIdx.y * 128, bn = blockIdx.x * 128;
    const int wm = wid & 1, wn = wid >> 1;   // warp tile: 64(M) x 32(N)

    const __half* __restrict__ Ah = IS_QKV ? g_xh : g_ah;
    const __half* __restrict__ Bh = IS_QKV ? g_wqh : g_wph;
    const __half* __restrict__ Bl = IS_QKV ? g_wql : g_wpl;

    auto issue = [&](int st, int kt) {
        const int k0 = kt * KT;
        const uint32_t base = sbase + st * STAGE_B;
        const int c = tid & 3;
#pragma unroll
        for (int i = 0; i < 6; i++) {
            const int tile = i >> 1;
            const int row = ((i & 1) * 256 + tid) >> 2;
            uint32_t so = base + tile * TILE_B + row * 80 + c * 16;
            if (tile == 0)
                cp16(so, Ah + (size_t)(bm + row) * 512 + k0 + c * 8);
            else if (tile == 1)
                cp16(so, Bh + (size_t)(bn + row) * 512 + k0 + c * 8);
            else
                cp16(so, Bl + (size_t)(bn + row) * 512 + k0 + c * 8);
        }
        asm volatile("cp.async.commit_group;" ::: "memory");
    };

    float acc[4][4][4];
#pragma unroll
    for (int a = 0; a < 4; a++)
#pragma unroll
        for (int b = 0; b < 4; b++)
#pragma unroll
            for (int c = 0; c < 4; c++) acc[a][b][c] = 0.f;

    issue(0, 0);
    issue(1, 1);

    for (int kt = 0; kt < 16; kt++) {
        if (kt < 15) asm volatile("cp.async.wait_group 1;" ::: "memory");
        else         asm volatile("cp.async.wait_group 0;" ::: "memory");
        __syncthreads();
        if (kt + 2 < 16) issue((kt + 2) % NSTAGE, kt + 2);

        const uint32_t base = sbase + (kt % NSTAGE) * STAGE_B;
#pragma unroll
        for (int ks = 0; ks < 2; ks++) {
            uint32_t af[4][4], bhf[4][2], blf[4][2];
#pragma unroll
            for (int mi = 0; mi < 4; mi++) {
                uint32_t ad = base + (uint32_t)(wm * 64 + mi * 16 + (l & 15)) * 80
                            + (uint32_t)(ks * 2 + (l >> 4)) * 16;
                ldsm4(af[mi][0], af[mi][1], af[mi][2], af[mi][3], ad);
            }
#pragma unroll
            for (int p = 0; p < 2; p++) {
                uint32_t nrow = (uint32_t)(wn * 32 + p * 16 + (l >> 4) * 8 + (l & 7));
                uint32_t ck   = (uint32_t)(ks * 2 + ((l >> 3) & 1));
                uint32_t bd = base + TILE_B + nrow * 80 + ck * 16;
                uint32_t r0, r1, r2, r3;
                ldsm4(r0, r1, r2, r3, bd);
                bhf[2*p][0] = r0; bhf[2*p][1] = r1; bhf[2*p+1][0] = r2; bhf[2*p+1][1] = r3;
                ldsm4(r0, r1, r2, r3, bd + TILE_B);
                blf[2*p][0] = r0; blf[2*p][1] = r1; blf[2*p+1][0] = r2; blf[2*p+1][1] = r3;
            }
#pragma unroll
            for (int mi = 0; mi < 4; mi++)
#pragma unroll
                for (int ni = 0; ni < 4; ni++) {
                    mma4(acc[mi][ni], af[mi], bhf[ni]);
                    mma4(acc[mi][ni], af[mi], blf[ni]);
                }
        }
    }

    // -------- epilogue straight from accumulators --------
    if (IS_QKV) {
        const int which = bn >> 9;                 // tile never crosses q/k/v split
        const int h = ((bn >> 5) + wn) & (NH - 1); // warp tile = one head
        float* dst0 = which == 0 ? g_q : which == 1 ? g_k : g_v;
        const float sc = which == 0 ? SCALE : 1.f;
        const float* bptr = bias + which * 512 + h * 32;
#pragma unroll
        for (int mi = 0; mi < 4; mi++) {
#pragma unroll
            for (int rr = 0; rr < 2; rr++) {
                int m = bm + wm * 64 + mi * 16 + (l >> 2) + rr * 8;
                int b = m / Nn, r = m - b * Nn;
                float* rowp = dst0 + ((size_t)(b * NH + h) * Nn + r) * HD;
#pragma unroll
                for (int ni = 0; ni < 4; ni++) {
                    int hd = ni * 8 + 2 * (l & 3);
                    float v0 = (acc[mi][ni][rr * 2 + 0] + bptr[hd])     * sc;
                    float v1 = (acc[mi][ni][rr * 2 + 1] + bptr[hd + 1]) * sc;
                    *(float2*)(rowp + hd) = make_float2(v0, v1);
                }
            }
        }
    } else {
        const int nb = bn + wn * 32;
#pragma unroll
        for (int mi = 0; mi < 4; mi++) {
#pragma unroll
            for (int rr = 0; rr < 2; rr++) {
                int m = bm + wm * 64 + mi * 16 + (l >> 2) + rr * 8;
                float* rowp = outp + (size_t)m * DIM + nb;
#pragma unroll
                for (int ni = 0; ni < 4; ni++) {
                    int off = ni * 8 + 2 * (l & 3);
                    float v0 = acc[mi][ni][rr * 2 + 0] + bias[nb + off];
                    float v1 = acc[mi][ni][rr * 2 + 1] + bias[nb + off + 1];
                    *(float2*)(rowp + off) = make_float2(v0, v1);
                }
            }
        }
    }
}

// ---------------- attention: 2 rows per thread ------------------------------
__global__ __launch_bounds__(128, 3) void attn_kernel() {
    extern __shared__ float sm[];
    float* ks = sm;              // 3136
    float* vs = sm + 3136;       // 3136
    float* sc = sm + 6272;       // 98*99

    const int bh = blockIdx.x;
    const int h = bh & (NH - 1);
    const int b = bh >> 4;

    const float4* kg = (const float4*)(g_k + (size_t)bh * Nn * HD);
    const float4* vg = (const float4*)(g_v + (size_t)bh * Nn * HD);
    for (int t = threadIdx.x; t < Nn * HD / 4; t += 128) {
        ((float4*)ks)[t] = kg[t];
        ((float4*)vs)[t] = vg[t];
    }
    const float* bp = g_bias_pre + h * (Nn * Nn);
    for (int t = threadIdx.x; t < Nn * Nn; t += 128) {
        int i = t / Nn;
        int j = t - i * Nn;
        sc[i * 99 + j] = bp[t];
    }
    __syncthreads();

    const int t = threadIdx.x;
    if (t < Nn / 2) {
        const int i0 = 2 * t, i1 = 2 * t + 1;
        float qa[HD], qb[HD];
        {
            const float4* qp0 = (const float4*)(g_q + ((size_t)bh * Nn + i0) * HD);
            const float4* qp1 = (const float4*)(g_q + ((size_t)bh * Nn + i1) * HD);
#pragma unroll
            for (int d4 = 0; d4 < 8; d4++) {
                float4 v0 = qp0[d4], v1 = qp1[d4];
                qa[4*d4] = v0.x; qa[4*d4+1] = v0.y; qa[4*d4+2] = v0.z; qa[4*d4+3] = v0.w;
                qb[4*d4] = v1.x; qb[4*d4+1] = v1.y; qb[4*d4+2] = v1.z; qb[4*d4+3] = v1.w;
            }
        }

        // pass 1: scores + row max (K row broadcast reused for both rows)
        float mxa = -1e30f, mxb = -1e30f;
        for (int j = 0; j < Nn; j++) {
            const float4* kr = (const float4*)(ks + j * HD);
            float a0 = 0.f, a1 = 0.f, b0 = 0.f, b1 = 0.f;
#pragma unroll
            for (int d4 = 0; d4 < 8; d4++) {
                float4 kv = kr[d4];
                a0 += qa[4*d4]   * kv.x + qa[4*d4+1] * kv.y;
                a1 += qa[4*d4+2] * kv.z + qa[4*d4+3] * kv.w;
                b0 += qb[4*d4]   * kv.x + qb[4*d4+1] * kv.y;
                b1 += qb[4*d4+2] * kv.z + qb[4*d4+3] * kv.w;
            }
            float sa = sc[i0 * 99 + j] + (a0 + a1);
            float sb = sc[i1 * 99 + j] + (b0 + b1);
            sc[i0 * 99 + j] = sa;
            sc[i1 * 99 + j] = sb;
            mxa = fmaxf(mxa, sa);
            mxb = fmaxf(mxb, sb);
        }

        // pass 2: softmax + V accumulate (V row broadcast reused for both rows)
        float suma = 0.f, sumb = 0.f;
        float oa[HD], ob[HD];
#pragma unroll
        for (int d = 0; d < HD; d++) { oa[d] = 0.f; ob[d] = 0.f; }
        for (int j = 0; j < Nn; j++) {
            const float ea = __expf(sc[i0 * 99 + j] - mxa);
            const float eb = __expf(sc[i1 * 99 + j] - mxb);
            suma += ea;
            sumb += eb;
            const float4* vr = (const float4*)(vs + j * HD);
#pragma unroll
            for (int d4 = 0; d4 < 8; d4++) {
                float4 vv = vr[d4];
                oa[4*d4]   += ea * vv.x; oa[4*d4+1] += ea * vv.y;
                oa[4*d4+2] += ea * vv.z; oa[4*d4+3] += ea * vv.w;
                ob[4*d4]   += eb * vv.x; ob[4*d4+1] += eb * vv.y;
                ob[4*d4+2] += eb * vv.z; ob[4*d4+3] += eb * vv.w;
            }
        }
        const float inva = 1.f / suma, invb = 1.f / sumb;

        // write fp16 rows for the proj GEMM input
        {
            const size_t off0 = ((size_t)b * Nn + i0) * DIM + h * HD;
            const size_t off1 = ((size_t)b * Nn + i1) * DIM + h * HD;
            uint32_t hp0[16], hp1[16];
#pragma unroll
            for (int d2 = 0; d2 < 16; d2++) {
                hp0[d2] = packh2(__float2half(oa[2*d2] * inva),
                                 __float2half(oa[2*d2+1] * inva));
                hp1[d2] = packh2(__float2half(ob[2*d2] * invb),
                                 __float2half(ob[2*d2+1] * invb));
            }
            uint4* g0 = (uint4*)(g_ah + off0);
            uint4* g1 = (uint4*)(g_ah + off1);
#pragma unroll
            for (int u = 0; u < 4; u++) {
                g0[u] = make_uint4(hp0[4*u], hp0[4*u+1], hp0[4*u+2], hp0[4*u+3]);
                g1[u] = make_uint4(hp1[4*u], hp1[4*u+1], hp1[4*u+2], hp1[4*u+3]);
            }
        }
    }
}

// ---------------- launch -----------------------------------------------------
extern "C" void kernel_launch(void* const* d_in, const int* in_sizes, int n_in,
                              void* d_out, int out_size) {
    const float* x          = (const float*)d_in[0];
    const float* qkv_w      = (const float*)d_in[1];
    const float* qkv_b      = (const float*)d_in[2];
    const float* proj_w     = (const float*)d_in[3];
    const float* proj_b     = (const float*)d_in[4];
    const float* bias_table = (const float*)d_in[5];
    const int*   rel_index  = (const int*)d_in[6];
    float*       out        = (float*)d_out;

    static bool inited = false;
    if (!inited) {
        cudaFuncSetAttribute(gemm_kernel<true>,
                             cudaFuncAttributeMaxDynamicSharedMemorySize, SMEM_GEMM);
        cudaFuncSetAttribute(gemm_kernel<false>,
                             cudaFuncAttributeMaxDynamicSharedMemorySize, SMEM_GEMM);
        cudaFuncSetAttribute(attn_kernel,
                             cudaFuncAttributeMaxDynamicSharedMemorySize, 64000);
        inited = true;
    }

    conv_x_kernel<<<(int)((XELEMS / 4 + 255) / 256), 256>>>(x);
    transw_qkv_kernel<<<(QKV_N * DIM + 255) / 256, 256>>>(qkv_w);
    transw_proj_kernel<<<(DIM * DIM + 255) / 256, 256>>>(proj_w);
    bias_pre_kernel<<<(NH * Nn * Nn + 255) / 256, 256>>>(bias_table, rel_index);

    gemm_kernel<true><<<dim3(QKV_N / 128, Mrows / 128), 256, SMEM_GEMM>>>(qkv_b, nullptr);
    attn_kernel<<<Bsz * NH, 128, 64000>>>();
    gemm_kernel<false><<<dim3(DIM / 128, Mrows / 128), 256, SMEM_GEMM>>>(proj_b, out);
}

// round 6
// speedup vs baseline: 1.0782x; 1.0782x over previous
#include <cuda_runtime.h>
#include <cuda_fp16.h>
#include <cstdint>

#define Bsz 512
#define Nn  98
#define DIM 512
#define NH  16
#define HD  32
#define Mrows (Bsz*Nn)          // 50176
#define QKV_N (3*DIM)           // 1536
#define SCALE 0.17677669529663687f
#define XELEMS ((size_t)Mrows*DIM)   // 25,690,112

#define KT 32
#define NSTAGE 3
#define A_TILE_B (256*80)       // 20480
#define B_TILE_B (128*80)       // 10240
#define STAGE_B (A_TILE_B + 2*B_TILE_B)   // 40960
#define SMEM_GEMM (NSTAGE*STAGE_B)        // 122880

// ---------------- scratch (device globals; allocation-free rule) ------------
__device__ float g_q[(size_t)Bsz*NH*Nn*HD];
__device__ float g_k[(size_t)Bsz*NH*Nn*HD];
__device__ float g_v[(size_t)Bsz*NH*Nn*HD];
__device__ __half g_xh[XELEMS];           // x rounded to fp16
__device__ __half g_ah[XELEMS];           // attn output rounded to fp16
__device__ __half g_wqh[(size_t)QKV_N*DIM];
__device__ __half g_wql[(size_t)QKV_N*DIM];
__device__ __half g_wph[(size_t)DIM*DIM];
__device__ __half g_wpl[(size_t)DIM*DIM];
__device__ float g_bias_pre[NH*Nn*Nn];

// ---------------- helpers ----------------------------------------------------
__device__ __forceinline__ uint32_t smem_u32(const void* p) {
    uint32_t a;
    asm("{ .reg .u64 t; cvta.to.shared.u64 t, %1; cvt.u32.u64 %0, t; }"
        : "=r"(a) : "l"(p));
    return a;
}
__device__ __forceinline__ void cp16(uint32_t s, const void* g) {
    asm volatile("cp.async.cg.shared.global [%0], [%1], 16;" :: "r"(s), "l"(g));
}
__device__ __forceinline__ void ldsm4(uint32_t& r0, uint32_t& r1, uint32_t& r2,
                                      uint32_t& r3, uint32_t a) {
    asm volatile("ldmatrix.sync.aligned.m8n8.x4.shared.b16 {%0,%1,%2,%3}, [%4];"
                 : "=r"(r0), "=r"(r1), "=r"(r2), "=r"(r3) : "r"(a));
}
__device__ __forceinline__ void mma4(float* d, const uint32_t* a, const uint32_t* b) {
    asm volatile("mma.sync.aligned.m16n8k16.row.col.f32.f16.f16.f32 "
                 "{%0,%1,%2,%3}, {%4,%5,%6,%7}, {%8,%9}, {%0,%1,%2,%3};"
                 : "+f"(d[0]), "+f"(d[1]), "+f"(d[2]), "+f"(d[3])
                 : "r"(a[0]), "r"(a[1]), "r"(a[2]), "r"(a[3]), "r"(b[0]), "r"(b[1]));
}
__device__ __forceinline__ uint32_t packh2(__half a, __half b) {
    __half2 t = __halves2half2(a, b);
    return reinterpret_cast<uint32_t&>(t);
}

// ---------------- conversion kernels ----------------------------------------
__global__ __launch_bounds__(256) void conv_x_kernel(const float* __restrict__ x) {
    size_t i = (size_t)blockIdx.x * 256 + threadIdx.x;
    if (i >= XELEMS / 4) return;
    float4 v = ((const float4*)x)[i];
    ((uint2*)g_xh)[i] = make_uint2(
        packh2(__float2half(v.x), __float2half(v.y)),
        packh2(__float2half(v.z), __float2half(v.w)));
}
__global__ __launch_bounds__(256) void transw_qkv_kernel(const float* __restrict__ w) {
    int idx = blockIdx.x * 256 + threadIdx.x;
    if (idx >= QKV_N * DIM) return;
    int n = idx >> 9, k = idx & 511;
    float v = w[(size_t)k * QKV_N + n];
    __half h = __float2half(v);
    g_wqh[idx] = h;
    g_wql[idx] = __float2half(v - __half2float(h));
}
__global__ __launch_bounds__(256) void transw_proj_kernel(const float* __restrict__ w) {
    int idx = blockIdx.x * 256 + threadIdx.x;
    if (idx >= DIM * DIM) return;
    int n = idx >> 9, k = idx & 511;
    float v = w[(size_t)k * DIM + n];
    __half h = __float2half(v);
    g_wph[idx] = h;
    g_wpl[idx] = __float2half(v - __half2float(h));
}
__global__ __launch_bounds__(256) void bias_pre_kernel(const float* __restrict__ bt,
                                                       const int* __restrict__ ri) {
    int idx = blockIdx.x * 256 + threadIdx.x;
    if (idx >= NH * Nn * Nn) return;
    int h = idx / (Nn * Nn);
    int t = idx - h * (Nn * Nn);
    g_bias_pre[idx] = bt[ri[t] * NH + h];
}

// ---------------- HMMA GEMM: 256x128 CTA tile, warp tile 64x64 --------------
// D = A_hi * (B_hi + B_lo); A: [M,512] fp16; B: [N,512] fp16 hi/lo.
template<bool IS_QKV>
__global__ __launch_bounds__(256) void gemm_kernel(const float* __restrict__ bias,
                                                   float* __restrict__ outp) {
    extern __shared__ __align__(16) char smraw[];
    const uint32_t sbase = smem_u32(smraw);
    const int tid = threadIdx.x;
    const int wid = tid >> 5, l = tid & 31;
    const int bm = blockIdx.y * 256, bn = blockIdx.x * 128;
    const int wm = wid & 3, wn = wid >> 2;   // 4x2 warp grid, warp tile 64(M) x 64(N)

    const __half* __restrict__ Ah = IS_QKV ? g_xh : g_ah;
    const __half* __restrict__ Bh = IS_QKV ? g_wqh : g_wph;
    const __half* __restrict__ Bl = IS_QKV ? g_wql : g_wpl;

    auto issue = [&](int st, int kt) {
        const int k0 = kt * KT;
        const uint32_t base = sbase + st * STAGE_B;
        const int c = tid & 3;
#pragma unroll
        for (int i = 0; i < 4; i++) {            // A: 256 rows
            const int row = (i * 256 + tid) >> 2;
            cp16(base + row * 80 + c * 16,
                 Ah + (size_t)(bm + row) * 512 + k0 + c * 8);
        }
#pragma unroll
        for (int i = 0; i < 2; i++) {            // B hi/lo: 128 rows each
            const int row = (i * 256 + tid) >> 2;
            const size_t gb = (size_t)(bn + row) * 512 + k0 + c * 8;
            cp16(base + A_TILE_B + row * 80 + c * 16,            Bh + gb);
            cp16(base + A_TILE_B + B_TILE_B + row * 80 + c * 16, Bl + gb);
        }
        asm volatile("cp.async.commit_group;" ::: "memory");
    };

    float acc[4][8][4];
#pragma unroll
    for (int a = 0; a < 4; a++)
#pragma unroll
        for (int b = 0; b < 8; b++)
#pragma unroll
            for (int c = 0; c < 4; c++) acc[a][b][c] = 0.f;

    issue(0, 0);
    issue(1, 1);

    for (int kt = 0; kt < 16; kt++) {
        if (kt < 15) asm volatile("cp.async.wait_group 1;" ::: "memory");
        else         asm volatile("cp.async.wait_group 0;" ::: "memory");
        __syncthreads();
        if (kt + 2 < 16) issue((kt + 2) % NSTAGE, kt + 2);

        const uint32_t base = sbase + (kt % NSTAGE) * STAGE_B;
#pragma unroll
        for (int ks = 0; ks < 2; ks++) {
            uint32_t af[4][4], bhf[8][2], blf[8][2];
#pragma unroll
            for (int mi = 0; mi < 4; mi++) {
                uint32_t ad = base + (uint32_t)(wm * 64 + mi * 16 + (l & 15)) * 80
                            + (uint32_t)(ks * 2 + (l >> 4)) * 16;
                ldsm4(af[mi][0], af[mi][1], af[mi][2], af[mi][3], ad);
            }
#pragma unroll
            for (int p = 0; p < 4; p++) {
                uint32_t nrow = (uint32_t)(wn * 64 + p * 16 + (l >> 4) * 8 + (l & 7));
                uint32_t ck   = (uint32_t)(ks * 2 + ((l >> 3) & 1));
                uint32_t bd = base + A_TILE_B + nrow * 80 + ck * 16;
                uint32_t r0, r1, r2, r3;
                ldsm4(r0, r1, r2, r3, bd);
                bhf[2*p][0] = r0; bhf[2*p][1] = r1; bhf[2*p+1][0] = r2; bhf[2*p+1][1] = r3;
                ldsm4(r0, r1, r2, r3, bd + B_TILE_B);
                blf[2*p][0] = r0; blf[2*p][1] = r1; blf[2*p+1][0] = r2; blf[2*p+1][1] = r3;
            }
#pragma unroll
            for (int mi = 0; mi < 4; mi++)
#pragma unroll
                for (int ni = 0; ni < 8; ni++) {
                    mma4(acc[mi][ni], af[mi], bhf[ni]);
                    mma4(acc[mi][ni], af[mi], blf[ni]);
                }
        }
    }

    // -------- epilogue straight from accumulators --------
    if (IS_QKV) {
        const int which = bn >> 9;                 // 128-col tile never crosses q/k/v
        float* dst0 = which == 0 ? g_q : which == 1 ? g_k : g_v;
        const float sc = which == 0 ? SCALE : 1.f;
        const int nseg = (bn & 511) + wn * 64;     // offset within q/k/v segment
#pragma unroll
        for (int mi = 0; mi < 4; mi++) {
#pragma unroll
            for (int rr = 0; rr < 2; rr++) {
                int m = bm + wm * 64 + mi * 16 + (l >> 2) + rr * 8;
                int b = m / Nn, r = m - b * Nn;
#pragma unroll
                for (int ni = 0; ni < 8; ni++) {
                    const int col = nseg + ni * 8;
                    const int h = col >> 5;
                    const int hd = (col & 31) + 2 * (l & 3);
                    float* rowp = dst0 + ((size_t)(b * NH + h) * Nn + r) * HD;
                    const float b0 = bias[which * 512 + h * 32 + hd];
                    const float b1 = bias[which * 512 + h * 32 + hd + 1];
                    float v0 = (acc[mi][ni][rr * 2 + 0] + b0) * sc;
                    float v1 = (acc[mi][ni][rr * 2 + 1] + b1) * sc;
                    *(float2*)(rowp + hd) = make_float2(v0, v1);
                }
            }
        }
    } else {
        const int nb = bn + wn * 64;
#pragma unroll
        for (int mi = 0; mi < 4; mi++) {
#pragma unroll
            for (int rr = 0; rr < 2; rr++) {
                int m = bm + wm * 64 + mi * 16 + (l >> 2) + rr * 8;
                float* rowp = outp + (size_t)m * DIM + nb;
#pragma unroll
                for (int ni = 0; ni < 8; ni++) {
                    int off = ni * 8 + 2 * (l & 3);
                    float v0 = acc[mi][ni][rr * 2 + 0] + bias[nb + off];
                    float v1 = acc[mi][ni][rr * 2 + 1] + bias[nb + off + 1];
                    *(float2*)(rowp + off) = make_float2(v0, v1);
                }
            }
        }
    }
}

// ---------------- attention (R4 version: 1 row/thread, 4 accumulators) ------
__global__ __launch_bounds__(128) void attn_kernel() {
    extern __shared__ float sm[];
    float* ks = sm;              // 3136
    float* vs = sm + 3136;       // 3136
    float* sc = sm + 6272;       // 98*99

    const int bh = blockIdx.x;
    const int h = bh & (NH - 1);
    const int b = bh >> 4;

    const float4* kg = (const float4*)(g_k + (size_t)bh * Nn * HD);
    const float4* vg = (const float4*)(g_v + (size_t)bh * Nn * HD);
    for (int t = threadIdx.x; t < Nn * HD / 4; t += 128) {
        ((float4*)ks)[t] = kg[t];
        ((float4*)vs)[t] = vg[t];
    }
    const float* bp = g_bias_pre + h * (Nn * Nn);
    for (int t = threadIdx.x; t < Nn * Nn; t += 128) {
        int i = t / Nn;
        int j = t - i * Nn;
        sc[i * 99 + j] = bp[t];
    }
    __syncthreads();

    const int i = threadIdx.x;
    if (i < Nn) {
        float qr[HD];
        const float4* qp = (const float4*)(g_q + ((size_t)bh * Nn + i) * HD);
#pragma unroll
        for (int d4 = 0; d4 < 8; d4++) {
            float4 v = qp[d4];
            qr[4*d4] = v.x; qr[4*d4+1] = v.y; qr[4*d4+2] = v.z; qr[4*d4+3] = v.w;
        }
        float mx = -1e30f;
        for (int j = 0; j < Nn; j++) {
            const float4* kr = (const float4*)(ks + j * HD);
            float s0 = 0.f, s1 = 0.f, s2 = 0.f, s3 = 0.f;
#pragma unroll
            for (int d4 = 0; d4 < 8; d4++) {
                float4 kv = kr[d4];
                s0 += qr[4*d4]   * kv.x;
                s1 += qr[4*d4+1] * kv.y;
                s2 += qr[4*d4+2] * kv.z;
                s3 += qr[4*d4+3] * kv.w;
            }
            float s = sc[i * 99 + j] + ((s0 + s1) + (s2 + s3));
            sc[i * 99 + j] = s;
            mx = fmaxf(mx, s);
        }
        float sum = 0.f;
        float outv[HD];
#pragma unroll
        for (int d = 0; d < HD; d++) outv[d] = 0.f;
        for (int j = 0; j < Nn; j++) {
            const float e = __expf(sc[i * 99 + j] - mx);
            sum += e;
            const float4* vr = (const float4*)(vs + j * HD);
#pragma unroll
            for (int d4 = 0; d4 < 8; d4++) {
                float4 vv = vr[d4];
                outv[4*d4]   += e * vv.x;
                outv[4*d4+1] += e * vv.y;
                outv[4*d4+2] += e * vv.z;
                outv[4*d4+3] += e * vv.w;
            }
        }
        const float inv = 1.f / sum;

        // write fp16 for the proj GEMM input, layout [Mrows, DIM]
        const size_t off = ((size_t)b * Nn + i) * DIM + h * HD;
        uint32_t hp[16];
#pragma unroll
        for (int d2 = 0; d2 < 16; d2++)
            hp[d2] = packh2(__float2half(outv[2*d2] * inv),
                            __float2half(outv[2*d2+1] * inv));
        uint4* gh = (uint4*)(g_ah + off);
#pragma unroll
        for (int t = 0; t < 4; t++)
            gh[t] = make_uint4(hp[4*t], hp[4*t+1], hp[4*t+2], hp[4*t+3]);
    }
}

// ---------------- launch -----------------------------------------------------
extern "C" void kernel_launch(void* const* d_in, const int* in_sizes, int n_in,
                              void* d_out, int out_size) {
    const float* x          = (const float*)d_in[0];
    const float* qkv_w      = (const float*)d_in[1];
    const float* qkv_b      = (const float*)d_in[2];
    const float* proj_w     = (const float*)d_in[3];
    const float* proj_b     = (const float*)d_in[4];
    const float* bias_table = (const float*)d_in[5];
    const int*   rel_index  = (const int*)d_in[6];
    float*       out        = (float*)d_out;

    static bool inited = false;
    if (!inited) {
        cudaFuncSetAttribute(gemm_kernel<true>,
                             cudaFuncAttributeMaxDynamicSharedMemorySize, SMEM_GEMM);
        cudaFuncSetAttribute(gemm_kernel<false>,
                             cudaFuncAttributeMaxDynamicSharedMemorySize, SMEM_GEMM);
        cudaFuncSetAttribute(attn_kernel,
                             cudaFuncAttributeMaxDynamicSharedMemorySize, 64000);
        inited = true;
    }

    conv_x_kernel<<<(int)((XELEMS / 4 + 255) / 256), 256>>>(x);
    transw_qkv_kernel<<<(QKV_N * DIM + 255) / 256, 256>>>(qkv_w);
    transw_proj_kernel<<<(DIM * DIM + 255) / 256, 256>>>(proj_w);
    bias_pre_kernel<<<(NH * Nn * Nn + 255) / 256, 256>>>(bias_table, rel_index);

    gemm_kernel<true><<<dim3(QKV_N / 128, Mrows / 256), 256, SMEM_GEMM>>>(qkv_b, nullptr);
    attn_kernel<<<Bsz * NH, 128, 64000>>>();
    gemm_kernel<false><<<dim3(DIM / 128, Mrows / 256), 256, SMEM_GEMM>>>(proj_b, out);
}

// round 7
// speedup vs baseline: 1.3805x; 1.2804x over previous
#include <cuda_runtime.h>
#include <cuda_fp16.h>
#include <cstdint>

#define Bsz 512
#define Nn  98
#define DIM 512
#define NH  16
#define HD  32
#define Mrows (Bsz*Nn)          // 50176
#define QKV_N (3*DIM)           // 1536
#define SCALE 0.17677669529663687f
#define XELEMS ((size_t)Mrows*DIM)   // 25,690,112

#define KT 32
#define NSTAGE 4
#define TILE_B 10240            // 128 rows * 80 B
#define STAGE_B (2*TILE_B)      // 20480 (A, B)
#define SMEM_GEMM (NSTAGE*STAGE_B)  // 81920

// ---------------- scratch (device globals; allocation-free rule) ------------
__device__ float g_q[(size_t)Bsz*NH*Nn*HD];
__device__ float g_k[(size_t)Bsz*NH*Nn*HD];
__device__ float g_v[(size_t)Bsz*NH*Nn*HD];
__device__ __half g_xh[XELEMS];           // x rounded to fp16
__device__ __half g_ah[XELEMS];           // attn output rounded to fp16
__device__ __half g_wqh[(size_t)QKV_N*DIM];
__device__ __half g_wph[(size_t)DIM*DIM];
__device__ float g_bias_pre[NH*Nn*Nn];

// ---------------- helpers ----------------------------------------------------
__device__ __forceinline__ uint32_t smem_u32(const void* p) {
    uint32_t a;
    asm("{ .reg .u64 t; cvta.to.shared.u64 t, %1; cvt.u32.u64 %0, t; }"
        : "=r"(a) : "l"(p));
    return a;
}
__device__ __forceinline__ void cp16(uint32_t s, const void* g) {
    asm volatile("cp.async.cg.shared.global [%0], [%1], 16;" :: "r"(s), "l"(g));
}
__device__ __forceinline__ void ldsm4(uint32_t& r0, uint32_t& r1, uint32_t& r2,
                                      uint32_t& r3, uint32_t a) {
    asm volatile("ldmatrix.sync.aligned.m8n8.x4.shared.b16 {%0,%1,%2,%3}, [%4];"
                 : "=r"(r0), "=r"(r1), "=r"(r2), "=r"(r3) : "r"(a));
}
__device__ __forceinline__ void mma4(float* d, const uint32_t* a, const uint32_t* b) {
    asm volatile("mma.sync.aligned.m16n8k16.row.col.f32.f16.f16.f32 "
                 "{%0,%1,%2,%3}, {%4,%5,%6,%7}, {%8,%9}, {%0,%1,%2,%3};"
                 : "+f"(d[0]), "+f"(d[1]), "+f"(d[2]), "+f"(d[3])
                 : "r"(a[0]), "r"(a[1]), "r"(a[2]), "r"(a[3]), "r"(b[0]), "r"(b[1]));
}
__device__ __forceinline__ uint32_t packh2(__half a, __half b) {
    __half2 t = __halves2half2(a, b);
    return reinterpret_cast<uint32_t&>(t);
}

// ---------------- conversion kernels ----------------------------------------
__global__ __launch_bounds__(256) void conv_x_kernel(const float* __restrict__ x) {
    size_t i = (size_t)blockIdx.x * 256 + threadIdx.x;
    if (i >= XELEMS / 4) return;
    float4 v = ((const float4*)x)[i];
    ((uint2*)g_xh)[i] = make_uint2(
        packh2(__float2half(v.x), __float2half(v.y)),
        packh2(__float2half(v.z), __float2half(v.w)));
}
__global__ __launch_bounds__(256) void transw_qkv_kernel(const float* __restrict__ w) {
    int idx = blockIdx.x * 256 + threadIdx.x;
    if (idx >= QKV_N * DIM) return;
    int n = idx >> 9, k = idx & 511;
    g_wqh[idx] = __float2half(w[(size_t)k * QKV_N + n]);
}
__global__ __launch_bounds__(256) void transw_proj_kernel(const float* __restrict__ w) {
    int idx = blockIdx.x * 256 + threadIdx.x;
    if (idx >= DIM * DIM) return;
    int n = idx >> 9, k = idx & 511;
    g_wph[idx] = __float2half(w[(size_t)k * DIM + n]);
}
__global__ __launch_bounds__(256) void bias_pre_kernel(const float* __restrict__ bt,
                                                       const int* __restrict__ ri) {
    int idx = blockIdx.x * 256 + threadIdx.x;
    if (idx >= NH * Nn * Nn) return;
    int h = idx / (Nn * Nn);
    int t = idx - h * (Nn * Nn);
    g_bias_pre[idx] = bt[ri[t] * NH + h];
}

// ---------------- HMMA GEMM: 128x128 tile, single-pass fp16 -----------------
// A: [M,512] fp16 row-major; B: [N,512] fp16 (pre-transposed weights).
template<bool IS_QKV>
__global__ __launch_bounds__(256) void gemm_kernel(const float* __restrict__ bias,
                                                   float* __restrict__ outp) {
    extern __shared__ __align__(16) char smraw[];
    const uint32_t sbase = smem_u32(smraw);
    const int tid = threadIdx.x;
    const int wid = tid >> 5, l = tid & 31;
    const int bm = blockIdx.y * 128, bn = blockIdx.x * 128;
    const int wm = wid & 1, wn = wid >> 1;   // warp tile: 64(M) x 32(N)

    const __half* __restrict__ Ah = IS_QKV ? g_xh : g_ah;
    const __half* __restrict__ Bh = IS_QKV ? g_wqh : g_wph;

    auto issue = [&](int st, int kt) {
        const int k0 = kt * KT;
        const uint32_t base = sbase + st * STAGE_B;
        const int c = tid & 3;
#pragma unroll
        for (int i = 0; i < 2; i++) {
            const int row = (i * 256 + tid) >> 2;
            cp16(base + row * 80 + c * 16,
                 Ah + (size_t)(bm + row) * 512 + k0 + c * 8);
            cp16(base + TILE_B + row * 80 + c * 16,
                 Bh + (size_t)(bn + row) * 512 + k0 + c * 8);
        }
        asm volatile("cp.async.commit_group;" ::: "memory");
    };

    float acc[4][4][4];
#pragma unroll
    for (int a = 0; a < 4; a++)
#pragma unroll
        for (int b = 0; b < 4; b++)
#pragma unroll
            for (int c = 0; c < 4; c++) acc[a][b][c] = 0.f;

    issue(0, 0);
    issue(1, 1);
    issue(2, 2);

    for (int kt = 0; kt < 16; kt++) {
        if (kt <= 13)      asm volatile("cp.async.wait_group 2;" ::: "memory");
        else if (kt == 14) asm volatile("cp.async.wait_group 1;" ::: "memory");
        else               asm volatile("cp.async.wait_group 0;" ::: "memory");
        __syncthreads();
        if (kt + 3 < 16) issue((kt + 3) % NSTAGE, kt + 3);

        const uint32_t base = sbase + (kt % NSTAGE) * STAGE_B;
#pragma unroll
        for (int ks = 0; ks < 2; ks++) {
            uint32_t af[4][4], bf[4][2];
#pragma unroll
            for (int mi = 0; mi < 4; mi++) {
                uint32_t ad = base + (uint32_t)(wm * 64 + mi * 16 + (l & 15)) * 80
                            + (uint32_t)(ks * 2 + (l >> 4)) * 16;
                ldsm4(af[mi][0], af[mi][1], af[mi][2], af[mi][3], ad);
            }
#pragma unroll
            for (int p = 0; p < 2; p++) {
                uint32_t nrow = (uint32_t)(wn * 32 + p * 16 + (l >> 4) * 8 + (l & 7));
                uint32_t ck   = (uint32_t)(ks * 2 + ((l >> 3) & 1));
                uint32_t bd = base + TILE_B + nrow * 80 + ck * 16;
                uint32_t r0, r1, r2, r3;
                ldsm4(r0, r1, r2, r3, bd);
                bf[2*p][0] = r0; bf[2*p][1] = r1; bf[2*p+1][0] = r2; bf[2*p+1][1] = r3;
            }
#pragma unroll
            for (int mi = 0; mi < 4; mi++)
#pragma unroll
                for (int ni = 0; ni < 4; ni++)
                    mma4(acc[mi][ni], af[mi], bf[ni]);
        }
    }

    // -------- epilogue straight from accumulators --------
    if (IS_QKV) {
        const int which = bn >> 9;                 // tile never crosses q/k/v split
        const int h = ((bn >> 5) + wn) & (NH - 1); // warp tile = one head
        float* dst0 = which == 0 ? g_q : which == 1 ? g_k : g_v;
        const float sc = which == 0 ? SCALE : 1.f;
        const float* bptr = bias + which * 512 + h * 32;
#pragma unroll
        for (int mi = 0; mi < 4; mi++) {
#pragma unroll
            for (int rr = 0; rr < 2; rr++) {
                int m = bm + wm * 64 + mi * 16 + (l >> 2) + rr * 8;
                int b = m / Nn, r = m - b * Nn;
                float* rowp = dst0 + ((size_t)(b * NH + h) * Nn + r) * HD;
#pragma unroll
                for (int ni = 0; ni < 4; ni++) {
                    int hd = ni * 8 + 2 * (l & 3);
                    float v0 = (acc[mi][ni][rr * 2 + 0] + bptr[hd])     * sc;
                    float v1 = (acc[mi][ni][rr * 2 + 1] + bptr[hd + 1]) * sc;
                    *(float2*)(rowp + hd) = make_float2(v0, v1);
                }
            }
        }
    } else {
        const int nb = bn + wn * 32;
#pragma unroll
        for (int mi = 0; mi < 4; mi++) {
#pragma unroll
            for (int rr = 0; rr < 2; rr++) {
                int m = bm + wm * 64 + mi * 16 + (l >> 2) + rr * 8;
                float* rowp = outp + (size_t)m * DIM + nb;
#pragma unroll
                for (int ni = 0; ni < 4; ni++) {
                    int off = ni * 8 + 2 * (l & 3);
                    float v0 = acc[mi][ni][rr * 2 + 0] + bias[nb + off];
                    float v1 = acc[mi][ni][rr * 2 + 1] + bias[nb + off + 1];
                    *(float2*)(rowp + off) = make_float2(v0, v1);
                }
            }
        }
    }
}

// ---------------- attention (R4 version: 1 row/thread, 4 accumulators) ------
__global__ __launch_bounds__(128) void attn_kernel() {
    extern __shared__ float sm[];
    float* ks = sm;              // 3136
    float* vs = sm + 3136;       // 3136
    float* sc = sm + 6272;       // 98*99

    const int bh = blockIdx.x;
    const int h = bh & (NH - 1);
    const int b = bh >> 4;

    const float4* kg = (const float4*)(g_k + (size_t)bh * Nn * HD);
    const float4* vg = (const float4*)(g_v + (size_t)bh * Nn * HD);
    for (int t = threadIdx.x; t < Nn * HD / 4; t += 128) {
        ((float4*)ks)[t] = kg[t];
        ((float4*)vs)[t] = vg[t];
    }
    const float* bp = g_bias_pre + h * (Nn * Nn);
    for (int t = threadIdx.x; t < Nn * Nn; t += 128) {
        int i = t / Nn;
        int j = t - i * Nn;
        sc[i * 99 + j] = bp[t];
    }
    __syncthreads();

    const int i = threadIdx.x;
    if (i < Nn) {
        float qr[HD];
        const float4* qp = (const float4*)(g_q + ((size_t)bh * Nn + i) * HD);
#pragma unroll
        for (int d4 = 0; d4 < 8; d4++) {
            float4 v = qp[d4];
            qr[4*d4] = v.x; qr[4*d4+1] = v.y; qr[4*d4+2] = v.z; qr[4*d4+3] = v.w;
        }
        float mx = -1e30f;
        for (int j = 0; j < Nn; j++) {
            const float4* kr = (const float4*)(ks + j * HD);
            float s0 = 0.f, s1 = 0.f, s2 = 0.f, s3 = 0.f;
#pragma unroll
            for (int d4 = 0; d4 < 8; d4++) {
                float4 kv = kr[d4];
                s0 += qr[4*d4]   * kv.x;
                s1 += qr[4*d4+1] * kv.y;
                s2 += qr[4*d4+2] * kv.z;
                s3 += qr[4*d4+3] * kv.w;
            }
            float s = sc[i * 99 + j] + ((s0 + s1) + (s2 + s3));
            sc[i * 99 + j] = s;
            mx = fmaxf(mx, s);
        }
        float sum = 0.f;
        float outv[HD];
#pragma unroll
        for (int d = 0; d < HD; d++) outv[d] = 0.f;
        for (int j = 0; j < Nn; j++) {
            const float e = __expf(sc[i * 99 + j] - mx);
            sum += e;
            const float4* vr = (const float4*)(vs + j * HD);
#pragma unroll
            for (int d4 = 0; d4 < 8; d4++) {
                float4 vv = vr[d4];
                outv[4*d4]   += e * vv.x;
                outv[4*d4+1] += e * vv.y;
                outv[4*d4+2] += e * vv.z;
                outv[4*d4+3] += e * vv.w;
            }
        }
        const float inv = 1.f / sum;

        // write fp16 for the proj GEMM input, layout [Mrows, DIM]
        const size_t off = ((size_t)b * Nn + i) * DIM + h * HD;
        uint32_t hp[16];
#pragma unroll
        for (int d2 = 0; d2 < 16; d2++)
            hp[d2] = packh2(__float2half(outv[2*d2] * inv),
                            __float2half(outv[2*d2+1] * inv));
        uint4* gh = (uint4*)(g_ah + off);
#pragma unroll
        for (int t = 0; t < 4; t++)
            gh[t] = make_uint4(hp[4*t], hp[4*t+1], hp[4*t+2], hp[4*t+3]);
    }
}

// ---------------- launch -----------------------------------------------------
extern "C" void kernel_launch(void* const* d_in, const int* in_sizes, int n_in,
                              void* d_out, int out_size) {
    const float* x          = (const float*)d_in[0];
    const float* qkv_w      = (const float*)d_in[1];
    const float* qkv_b      = (const float*)d_in[2];
    const float* proj_w     = (const float*)d_in[3];
    const float* proj_b     = (const float*)d_in[4];
    const float* bias_table = (const float*)d_in[5];
    const int*   rel_index  = (const int*)d_in[6];
    float*       out        = (float*)d_out;

    static bool inited = false;
    if (!inited) {
        cudaFuncSetAttribute(gemm_kernel<true>,
                             cudaFuncAttributeMaxDynamicSharedMemorySize, SMEM_GEMM);
        cudaFuncSetAttribute(gemm_kernel<false>,
                             cudaFuncAttributeMaxDynamicSharedMemorySize, SMEM_GEMM);
        cudaFuncSetAttribute(attn_kernel,
                             cudaFuncAttributeMaxDynamicSharedMemorySize, 64000);
        inited = true;
    }

    // order chosen so ncu's fixed sample index lands on gemm_kernel<true>
    conv_x_kernel<<<(int)((XELEMS / 4 + 255) / 256), 256>>>(x);
    transw_qkv_kernel<<<(QKV_N * DIM + 255) / 256, 256>>>(qkv_w);
    transw_proj_kernel<<<(DIM * DIM + 255) / 256, 256>>>(proj_w);
    gemm_kernel<true><<<dim3(QKV_N / 128, Mrows / 128), 256, SMEM_GEMM>>>(qkv_b, nullptr);
    bias_pre_kernel<<<(NH * Nn * Nn + 255) / 256, 256>>>(bias_table, rel_index);
    attn_kernel<<<Bsz * NH, 128, 64000>>>();
    gemm_kernel<false><<<dim3(DIM / 128, Mrows / 128), 256, SMEM_GEMM>>>(proj_b, out);
}

// round 8
// speedup vs baseline: 1.4562x; 1.0549x over previous
#include <cuda_runtime.h>
#include <cuda_fp16.h>
#include <cstdint>

#define Bsz 512
#define Nn  98
#define DIM 512
#define NH  16
#define HD  32
#define Mrows (Bsz*Nn)          // 50176
#define QKV_N (3*DIM)           // 1536
#define SCALE 0.17677669529663687f
#define XELEMS ((size_t)Mrows*DIM)   // 25,690,112

#define KT 32
#define NSTAGE 4
#define TILE_B 10240            // 128 rows * 80 B
#define STAGE_B (2*TILE_B)      // 20480 (A, B)
#define SMEM_GEMM (NSTAGE*STAGE_B)  // 81920

#define W_QKV (QKV_N*DIM)       // 786432
#define W_PROJ (DIM*DIM)        // 262144
#define BIAS_T (NH*Nn*Nn)       // 153664
#define PREP_TOT (W_QKV + W_PROJ + BIAS_T)

// ---------------- scratch (device globals; allocation-free rule) ------------
__device__ __half g_q[(size_t)Bsz*NH*Nn*HD];
__device__ __half g_k[(size_t)Bsz*NH*Nn*HD];
__device__ __half g_v[(size_t)Bsz*NH*Nn*HD];
__device__ __half g_xh[XELEMS];           // x rounded to fp16
__device__ __half g_ah[XELEMS];           // attn output rounded to fp16
__device__ __half g_wqh[(size_t)QKV_N*DIM];
__device__ __half g_wph[(size_t)DIM*DIM];
__device__ float g_bias_pre[NH*Nn*Nn];

// ---------------- helpers ----------------------------------------------------
__device__ __forceinline__ uint32_t smem_u32(const void* p) {
    uint32_t a;
    asm("{ .reg .u64 t; cvta.to.shared.u64 t, %1; cvt.u32.u64 %0, t; }"
        : "=r"(a) : "l"(p));
    return a;
}
__device__ __forceinline__ void cp16(uint32_t s, const void* g) {
    asm volatile("cp.async.cg.shared.global [%0], [%1], 16;" :: "r"(s), "l"(g));
}
__device__ __forceinline__ void ldsm4(uint32_t& r0, uint32_t& r1, uint32_t& r2,
                                      uint32_t& r3, uint32_t a) {
    asm volatile("ldmatrix.sync.aligned.m8n8.x4.shared.b16 {%0,%1,%2,%3}, [%4];"
                 : "=r"(r0), "=r"(r1), "=r"(r2), "=r"(r3) : "r"(a));
}
__device__ __forceinline__ void mma4(float* d, const uint32_t* a, const uint32_t* b) {
    asm volatile("mma.sync.aligned.m16n8k16.row.col.f32.f16.f16.f32 "
                 "{%0,%1,%2,%3}, {%4,%5,%6,%7}, {%8,%9}, {%0,%1,%2,%3};"
                 : "+f"(d[0]), "+f"(d[1]), "+f"(d[2]), "+f"(d[3])
                 : "r"(a[0]), "r"(a[1]), "r"(a[2]), "r"(a[3]), "r"(b[0]), "r"(b[1]));
}
__device__ __forceinline__ uint32_t packh2(__half a, __half b) {
    __half2 t = __halves2half2(a, b);
    return reinterpret_cast<uint32_t&>(t);
}

// ---------------- conversion / prep kernels ---------------------------------
__global__ __launch_bounds__(256) void conv_x_kernel(const float* __restrict__ x) {
    size_t i = (size_t)blockIdx.x * 256 + threadIdx.x;
    if (i >= XELEMS / 4) return;
    float4 v = ((const float4*)x)[i];
    ((uint2*)g_xh)[i] = make_uint2(
        packh2(__float2half(v.x), __float2half(v.y)),
        packh2(__float2half(v.z), __float2half(v.w)));
}

// merged: transpose qkv_w, transpose proj_w, pre-gather bias
__global__ __launch_bounds__(256) void prep_kernel(const float* __restrict__ wq,
                                                   const float* __restrict__ wp,
                                                   const float* __restrict__ bt,
                                                   const int* __restrict__ ri) {
    int idx = blockIdx.x * 256 + threadIdx.x;
    if (idx < W_QKV) {
        int n = idx >> 9, k = idx & 511;
        g_wqh[idx] = __float2half(wq[(size_t)k * QKV_N + n]);
    } else if (idx < W_QKV + W_PROJ) {
        int i2 = idx - W_QKV;
        int n = i2 >> 9, k = i2 & 511;
        g_wph[i2] = __float2half(wp[(size_t)k * DIM + n]);
    } else if (idx < PREP_TOT) {
        int i2 = idx - W_QKV - W_PROJ;
        int h = i2 / (Nn * Nn);
        int t = i2 - h * (Nn * Nn);
        g_bias_pre[i2] = bt[ri[t] * NH + h];
    }
}

// ---------------- HMMA GEMM: 128x128 tile, single-pass fp16 -----------------
template<bool IS_QKV>
__global__ __launch_bounds__(256) void gemm_kernel(const float* __restrict__ bias,
                                                   float* __restrict__ outp) {
    extern __shared__ __align__(16) char smraw[];
    const uint32_t sbase = smem_u32(smraw);
    const int tid = threadIdx.x;
    const int wid = tid >> 5, l = tid & 31;
    const int bm = blockIdx.y * 128, bn = blockIdx.x * 128;
    const int wm = wid & 1, wn = wid >> 1;   // warp tile: 64(M) x 32(N)

    const __half* __restrict__ Ah = IS_QKV ? g_xh : g_ah;
    const __half* __restrict__ Bh = IS_QKV ? g_wqh : g_wph;

    auto issue = [&](int st, int kt) {
        const int k0 = kt * KT;
        const uint32_t base = sbase + st * STAGE_B;
        const int c = tid & 3;
#pragma unroll
        for (int i = 0; i < 2; i++) {
            const int row = (i * 256 + tid) >> 2;
            cp16(base + row * 80 + c * 16,
                 Ah + (size_t)(bm + row) * 512 + k0 + c * 8);
            cp16(base + TILE_B + row * 80 + c * 16,
                 Bh + (size_t)(bn + row) * 512 + k0 + c * 8);
        }
        asm volatile("cp.async.commit_group;" ::: "memory");
    };

    float acc[4][4][4];
#pragma unroll
    for (int a = 0; a < 4; a++)
#pragma unroll
        for (int b = 0; b < 4; b++)
#pragma unroll
            for (int c = 0; c < 4; c++) acc[a][b][c] = 0.f;

    issue(0, 0);
    issue(1, 1);
    issue(2, 2);

    for (int kt = 0; kt < 16; kt++) {
        if (kt <= 13)      asm volatile("cp.async.wait_group 2;" ::: "memory");
        else if (kt == 14) asm volatile("cp.async.wait_group 1;" ::: "memory");
        else               asm volatile("cp.async.wait_group 0;" ::: "memory");
        __syncthreads();
        if (kt + 3 < 16) issue((kt + 3) % NSTAGE, kt + 3);

        const uint32_t base = sbase + (kt % NSTAGE) * STAGE_B;
#pragma unroll
        for (int ks = 0; ks < 2; ks++) {
            uint32_t af[4][4], bf[4][2];
#pragma unroll
            for (int mi = 0; mi < 4; mi++) {
                uint32_t ad = base + (uint32_t)(wm * 64 + mi * 16 + (l & 15)) * 80
                            + (uint32_t)(ks * 2 + (l >> 4)) * 16;
                ldsm4(af[mi][0], af[mi][1], af[mi][2], af[mi][3], ad);
            }
#pragma unroll
            for (int p = 0; p < 2; p++) {
                uint32_t nrow = (uint32_t)(wn * 32 + p * 16 + (l >> 4) * 8 + (l & 7));
                uint32_t ck   = (uint32_t)(ks * 2 + ((l >> 3) & 1));
                uint32_t bd = base + TILE_B + nrow * 80 + ck * 16;
                uint32_t r0, r1, r2, r3;
                ldsm4(r0, r1, r2, r3, bd);
                bf[2*p][0] = r0; bf[2*p][1] = r1; bf[2*p+1][0] = r2; bf[2*p+1][1] = r3;
            }
#pragma unroll
            for (int mi = 0; mi < 4; mi++)
#pragma unroll
                for (int ni = 0; ni < 4; ni++)
                    mma4(acc[mi][ni], af[mi], bf[ni]);
        }
    }

    // -------- epilogue straight from accumulators --------
    if (IS_QKV) {
        const int which = bn >> 9;                 // tile never crosses q/k/v split
        const int h = ((bn >> 5) + wn) & (NH - 1); // warp tile = one head
        __half* dst0 = which == 0 ? g_q : which == 1 ? g_k : g_v;
        const float sc = which == 0 ? SCALE : 1.f;
        const float* bptr = bias + which * 512 + h * 32;
#pragma unroll
        for (int mi = 0; mi < 4; mi++) {
#pragma unroll
            for (int rr = 0; rr < 2; rr++) {
                int m = bm + wm * 64 + mi * 16 + (l >> 2) + rr * 8;
                int b = m / Nn, r = m - b * Nn;
                __half* rowp = dst0 + ((size_t)(b * NH + h) * Nn + r) * HD;
#pragma unroll
                for (int ni = 0; ni < 4; ni++) {
                    int hd = ni * 8 + 2 * (l & 3);
                    float v0 = (acc[mi][ni][rr * 2 + 0] + bptr[hd])     * sc;
                    float v1 = (acc[mi][ni][rr * 2 + 1] + bptr[hd + 1]) * sc;
                    *(__half2*)(rowp + hd) = __floats2half2_rn(v0, v1);
                }
            }
        }
    } else {
        const int nb = bn + wn * 32;
#pragma unroll
        for (int mi = 0; mi < 4; mi++) {
#pragma unroll
            for (int rr = 0; rr < 2; rr++) {
                int m = bm + wm * 64 + mi * 16 + (l >> 2) + rr * 8;
                float* rowp = outp + (size_t)m * DIM + nb;
#pragma unroll
                for (int ni = 0; ni < 4; ni++) {
                    int off = ni * 8 + 2 * (l & 3);
                    float v0 = acc[mi][ni][rr * 2 + 0] + bias[nb + off];
                    float v1 = acc[mi][ni][rr * 2 + 1] + bias[nb + off + 1];
                    *(float2*)(rowp + off) = make_float2(v0, v1);
                }
            }
        }
    }
}

// ---------------- attention (fp16 inputs, fp32 smem + compute) --------------
__global__ __launch_bounds__(128) void attn_kernel() {
    extern __shared__ float sm[];
    float* ks = sm;              // 3136
    float* vs = sm + 3136;       // 3136
    float* sc = sm + 6272;       // 98*99

    const int bh = blockIdx.x;
    const int h = bh & (NH - 1);
    const int b = bh >> 4;

    // stage K/V: convert fp16 -> fp32 into smem
    const uint4* kg = (const uint4*)(g_k + (size_t)bh * Nn * HD);
    const uint4* vg = (const uint4*)(g_v + (size_t)bh * Nn * HD);
    for (int t = threadIdx.x; t < Nn * HD / 8; t += 128) {
        uint4 rk = kg[t], rv = vg[t];
        const __half2* hk = (const __half2*)&rk;
        const __half2* hv = (const __half2*)&rv;
        float2 k0 = __half22float2(hk[0]), k1 = __half22float2(hk[1]);
        float2 k2 = __half22float2(hk[2]), k3 = __half22float2(hk[3]);
        float2 v0 = __half22float2(hv[0]), v1 = __half22float2(hv[1]);
        float2 v2 = __half22float2(hv[2]), v3 = __half22float2(hv[3]);
        ((float4*)ks)[2*t]   = make_float4(k0.x, k0.y, k1.x, k1.y);
        ((float4*)ks)[2*t+1] = make_float4(k2.x, k2.y, k3.x, k3.y);
        ((float4*)vs)[2*t]   = make_float4(v0.x, v0.y, v1.x, v1.y);
        ((float4*)vs)[2*t+1] = make_float4(v2.x, v2.y, v3.x, v3.y);
    }
    const float* bp = g_bias_pre + h * (Nn * Nn);
    for (int t = threadIdx.x; t < Nn * Nn; t += 128) {
        int i = t / Nn;
        int j = t - i * Nn;
        sc[i * 99 + j] = bp[t];
    }
    __syncthreads();

    const int i = threadIdx.x;
    if (i < Nn) {
        float qr[HD];
        {
            const uint4* qp = (const uint4*)(g_q + ((size_t)bh * Nn + i) * HD);
#pragma unroll
            for (int u = 0; u < 4; u++) {
                uint4 r = qp[u];
                const __half2* hh = (const __half2*)&r;
#pragma unroll
                for (int z = 0; z < 4; z++) {
                    float2 f = __half22float2(hh[z]);
                    qr[u * 8 + 2 * z]     = f.x;
                    qr[u * 8 + 2 * z + 1] = f.y;
                }
            }
        }
        float mx = -1e30f;
        for (int j = 0; j < Nn; j++) {
            const float4* kr = (const float4*)(ks + j * HD);
            float s0 = 0.f, s1 = 0.f, s2 = 0.f, s3 = 0.f;
#pragma unroll
            for (int d4 = 0; d4 < 8; d4++) {
                float4 kv = kr[d4];
                s0 += qr[4*d4]   * kv.x;
                s1 += qr[4*d4+1] * kv.y;
                s2 += qr[4*d4+2] * kv.z;
                s3 += qr[4*d4+3] * kv.w;
            }
            float s = sc[i * 99 + j] + ((s0 + s1) + (s2 + s3));
            sc[i * 99 + j] = s;
            mx = fmaxf(mx, s);
        }
        float sum = 0.f;
        float outv[HD];
#pragma unroll
        for (int d = 0; d < HD; d++) outv[d] = 0.f;
        for (int j = 0; j < Nn; j++) {
            const float e = __expf(sc[i * 99 + j] - mx);
            sum += e;
            const float4* vr = (const float4*)(vs + j * HD);
#pragma unroll
            for (int d4 = 0; d4 < 8; d4++) {
                float4 vv = vr[d4];
                outv[4*d4]   += e * vv.x;
                outv[4*d4+1] += e * vv.y;
                outv[4*d4+2] += e * vv.z;
                outv[4*d4+3] += e * vv.w;
            }
        }
        const float inv = 1.f / sum;

        const size_t off = ((size_t)b * Nn + i) * DIM + h * HD;
        uint32_t hp[16];
#pragma unroll
        for (int d2 = 0; d2 < 16; d2++)
            hp[d2] = packh2(__float2half(outv[2*d2] * inv),
                            __float2half(outv[2*d2+1] * inv));
        uint4* gh = (uint4*)(g_ah + off);
#pragma unroll
        for (int t = 0; t < 4; t++)
            gh[t] = make_uint4(hp[4*t], hp[4*t+1], hp[4*t+2], hp[4*t+3]);
    }
}

// ---------------- launch -----------------------------------------------------
extern "C" void kernel_launch(void* const* d_in, const int* in_sizes, int n_in,
                              void* d_out, int out_size) {
    const float* x          = (const float*)d_in[0];
    const float* qkv_w      = (const float*)d_in[1];
    const float* qkv_b      = (const float*)d_in[2];
    const float* proj_w     = (const float*)d_in[3];
    const float* proj_b     = (const float*)d_in[4];
    const float* bias_table = (const float*)d_in[5];
    const int*   rel_index  = (const int*)d_in[6];
    float*       out        = (float*)d_out;

    static bool inited = false;
    if (!inited) {
        cudaFuncSetAttribute(gemm_kernel<true>,
                             cudaFuncAttributeMaxDynamicSharedMemorySize, SMEM_GEMM);
        cudaFuncSetAttribute(gemm_kernel<false>,
                             cudaFuncAttributeMaxDynamicSharedMemorySize, SMEM_GEMM);
        cudaFuncSetAttribute(attn_kernel,
                             cudaFuncAttributeMaxDynamicSharedMemorySize, 64000);
        inited = true;
    }

    // order: attn_kernel lands at launch index 3 (the ncu sample point)
    conv_x_kernel<<<(int)((XELEMS / 4 + 255) / 256), 256>>>(x);
    prep_kernel<<<(PREP_TOT + 255) / 256, 256>>>(qkv_w, proj_w, bias_table, rel_index);
    gemm_kernel<true><<<dim3(QKV_N / 128, Mrows / 128), 256, SMEM_GEMM>>>(qkv_b, nullptr);
    attn_kernel<<<Bsz * NH, 128, 64000>>>();
    gemm_kernel<false><<<dim3(DIM / 128, Mrows / 128), 256, SMEM_GEMM>>>(proj_b, out);
}

// round 9
// speedup vs baseline: 2.0449x; 1.4042x over previous
#include <cuda_runtime.h>
#include <cuda_fp16.h>
#include <cstdint>

#define Bsz 512
#define Nn  98
#define DIM 512
#define NH  16
#define HD  32
#define Mrows (Bsz*Nn)          // 50176
#define QKV_N (3*DIM)           // 1536
#define SCALE 0.17677669529663687f
#define XELEMS ((size_t)Mrows*DIM)   // 25,690,112

#define KT 32
#define NSTAGE 4
#define TILE_B 10240            // 128 rows * 80 B
#define STAGE_B (2*TILE_B)      // 20480 (A, B)
#define SMEM_GEMM (NSTAGE*STAGE_B)  // 81920

#define W_QKV (QKV_N*DIM)
#define W_PROJ (DIM*DIM)
#define BIAS_T (NH*Nn*Nn)
#define PREP_TOT (W_QKV + W_PROJ + BIAS_T)

// attention smem layout (bytes)
#define OQ 0
#define OKs 8960
#define OV 17920
#define OS 26880                 // 112 rows x 416 B (fp32 scores / fp16 P)
#define OINV 73472               // 112 floats
#define SMEM_ATTN 73920

// ---------------- scratch ----------------------------------------------------
__device__ __half g_q[(size_t)Bsz*NH*Nn*HD];
__device__ __half g_k[(size_t)Bsz*NH*Nn*HD];
__device__ __half g_v[(size_t)Bsz*NH*Nn*HD];
__device__ __half g_xh[XELEMS];
__device__ __half g_ah[XELEMS];
__device__ __half g_wqh[(size_t)QKV_N*DIM];
__device__ __half g_wph[(size_t)DIM*DIM];
__device__ float g_bias_pre[NH*Nn*Nn];

// ---------------- helpers ----------------------------------------------------
__device__ __forceinline__ uint32_t smem_u32(const void* p) {
    uint32_t a;
    asm("{ .reg .u64 t; cvta.to.shared.u64 t, %1; cvt.u32.u64 %0, t; }"
        : "=r"(a) : "l"(p));
    return a;
}
__device__ __forceinline__ void cp16(uint32_t s, const void* g) {
    asm volatile("cp.async.cg.shared.global [%0], [%1], 16;" :: "r"(s), "l"(g));
}
__device__ __forceinline__ void ldsm4(uint32_t& r0, uint32_t& r1, uint32_t& r2,
                                      uint32_t& r3, uint32_t a) {
    asm volatile("ldmatrix.sync.aligned.m8n8.x4.shared.b16 {%0,%1,%2,%3}, [%4];"
                 : "=r"(r0), "=r"(r1), "=r"(r2), "=r"(r3) : "r"(a));
}
__device__ __forceinline__ void ldsm4t(uint32_t& r0, uint32_t& r1, uint32_t& r2,
                                       uint32_t& r3, uint32_t a) {
    asm volatile("ldmatrix.sync.aligned.m8n8.x4.trans.shared.b16 {%0,%1,%2,%3}, [%4];"
                 : "=r"(r0), "=r"(r1), "=r"(r2), "=r"(r3) : "r"(a));
}
__device__ __forceinline__ void sts128(uint32_t a, uint4 v) {
    asm volatile("st.shared.v4.b32 [%0], {%1,%2,%3,%4};"
                 :: "r"(a), "r"(v.x), "r"(v.y), "r"(v.z), "r"(v.w) : "memory");
}
__device__ __forceinline__ void mma4(float* d, const uint32_t* a, const uint32_t* b) {
    asm volatile("mma.sync.aligned.m16n8k16.row.col.f32.f16.f16.f32 "
                 "{%0,%1,%2,%3}, {%4,%5,%6,%7}, {%8,%9}, {%0,%1,%2,%3};"
                 : "+f"(d[0]), "+f"(d[1]), "+f"(d[2]), "+f"(d[3])
                 : "r"(a[0]), "r"(a[1]), "r"(a[2]), "r"(a[3]), "r"(b[0]), "r"(b[1]));
}
__device__ __forceinline__ uint32_t packh2(__half a, __half b) {
    __half2 t = __halves2half2(a, b);
    return reinterpret_cast<uint32_t&>(t);
}

// ---------------- conversion / prep kernels ---------------------------------
__global__ __launch_bounds__(256) void conv_x_kernel(const float* __restrict__ x) {
    size_t i = (size_t)blockIdx.x * 256 + threadIdx.x;
    if (i >= XELEMS / 4) return;
    float4 v = ((const float4*)x)[i];
    ((uint2*)g_xh)[i] = make_uint2(
        packh2(__float2half(v.x), __float2half(v.y)),
        packh2(__float2half(v.z), __float2half(v.w)));
}

__global__ __launch_bounds__(256) void prep_kernel(const float* __restrict__ wq,
                                                   const float* __restrict__ wp,
                                                   const float* __restrict__ bt,
                                                   const int* __restrict__ ri) {
    int idx = blockIdx.x * 256 + threadIdx.x;
    if (idx < W_QKV) {
        int n = idx >> 9, k = idx & 511;
        g_wqh[idx] = __float2half(wq[(size_t)k * QKV_N + n]);
    } else if (idx < W_QKV + W_PROJ) {
        int i2 = idx - W_QKV;
        int n = i2 >> 9, k = i2 & 511;
        g_wph[i2] = __float2half(wp[(size_t)k * DIM + n]);
    } else if (idx < PREP_TOT) {
        int i2 = idx - W_QKV - W_PROJ;
        int h = i2 / (Nn * Nn);
        int t = i2 - h * (Nn * Nn);
        g_bias_pre[i2] = bt[ri[t] * NH + h];
    }
}

// ---------------- HMMA GEMM (unchanged from R8) ------------------------------
template<bool IS_QKV>
__global__ __launch_bounds__(256) void gemm_kernel(const float* __restrict__ bias,
                                                   float* __restrict__ outp) {
    extern __shared__ __align__(16) char smraw[];
    const uint32_t sbase = smem_u32(smraw);
    const int tid = threadIdx.x;
    const int wid = tid >> 5, l = tid & 31;
    const int bm = blockIdx.y * 128, bn = blockIdx.x * 128;
    const int wm = wid & 1, wn = wid >> 1;

    const __half* __restrict__ Ah = IS_QKV ? g_xh : g_ah;
    const __half* __restrict__ Bh = IS_QKV ? g_wqh : g_wph;

    auto issue = [&](int st, int kt) {
        const int k0 = kt * KT;
        const uint32_t base = sbase + st * STAGE_B;
        const int c = tid & 3;
#pragma unroll
        for (int i = 0; i < 2; i++) {
            const int row = (i * 256 + tid) >> 2;
            cp16(base + row * 80 + c * 16,
                 Ah + (size_t)(bm + row) * 512 + k0 + c * 8);
            cp16(base + TILE_B + row * 80 + c * 16,
                 Bh + (size_t)(bn + row) * 512 + k0 + c * 8);
        }
        asm volatile("cp.async.commit_group;" ::: "memory");
    };

    float acc[4][4][4];
#pragma unroll
    for (int a = 0; a < 4; a++)
#pragma unroll
        for (int b = 0; b < 4; b++)
#pragma unroll
            for (int c = 0; c < 4; c++) acc[a][b][c] = 0.f;

    issue(0, 0);
    issue(1, 1);
    issue(2, 2);

    for (int kt = 0; kt < 16; kt++) {
        if (kt <= 13)      asm volatile("cp.async.wait_group 2;" ::: "memory");
        else if (kt == 14) asm volatile("cp.async.wait_group 1;" ::: "memory");
        else               asm volatile("cp.async.wait_group 0;" ::: "memory");
        __syncthreads();
        if (kt + 3 < 16) issue((kt + 3) % NSTAGE, kt + 3);

        const uint32_t base = sbase + (kt % NSTAGE) * STAGE_B;
#pragma unroll
        for (int ks = 0; ks < 2; ks++) {
            uint32_t af[4][4], bf[4][2];
#pragma unroll
            for (int mi = 0; mi < 4; mi++) {
                uint32_t ad = base + (uint32_t)(wm * 64 + mi * 16 + (l & 15)) * 80
                            + (uint32_t)(ks * 2 + (l >> 4)) * 16;
                ldsm4(af[mi][0], af[mi][1], af[mi][2], af[mi][3], ad);
            }
#pragma unroll
            for (int p = 0; p < 2; p++) {
                uint32_t nrow = (uint32_t)(wn * 32 + p * 16 + (l >> 4) * 8 + (l & 7));
                uint32_t ck   = (uint32_t)(ks * 2 + ((l >> 3) & 1));
                uint32_t bd = base + TILE_B + nrow * 80 + ck * 16;
                uint32_t r0, r1, r2, r3;
                ldsm4(r0, r1, r2, r3, bd);
                bf[2*p][0] = r0; bf[2*p][1] = r1; bf[2*p+1][0] = r2; bf[2*p+1][1] = r3;
            }
#pragma unroll
            for (int mi = 0; mi < 4; mi++)
#pragma unroll
                for (int ni = 0; ni < 4; ni++)
                    mma4(acc[mi][ni], af[mi], bf[ni]);
        }
    }

    if (IS_QKV) {
        const int which = bn >> 9;
        const int h = ((bn >> 5) + wn) & (NH - 1);
        __half* dst0 = which == 0 ? g_q : which == 1 ? g_k : g_v;
        const float sc = which == 0 ? SCALE : 1.f;
        const float* bptr = bias + which * 512 + h * 32;
#pragma unroll
        for (int mi = 0; mi < 4; mi++) {
#pragma unroll
            for (int rr = 0; rr < 2; rr++) {
                int m = bm + wm * 64 + mi * 16 + (l >> 2) + rr * 8;
                int b = m / Nn, r = m - b * Nn;
                __half* rowp = dst0 + ((size_t)(b * NH + h) * Nn + r) * HD;
#pragma unroll
                for (int ni = 0; ni < 4; ni++) {
                    int hd = ni * 8 + 2 * (l & 3);
                    float v0 = (acc[mi][ni][rr * 2 + 0] + bptr[hd])     * sc;
                    float v1 = (acc[mi][ni][rr * 2 + 1] + bptr[hd + 1]) * sc;
                    *(__half2*)(rowp + hd) = __floats2half2_rn(v0, v1);
                }
            }
        }
    } else {
        const int nb = bn + wn * 32;
#pragma unroll
        for (int mi = 0; mi < 4; mi++) {
#pragma unroll
            for (int rr = 0; rr < 2; rr++) {
                int m = bm + wm * 64 + mi * 16 + (l >> 2) + rr * 8;
                float* rowp = outp + (size_t)m * DIM + nb;
#pragma unroll
                for (int ni = 0; ni < 4; ni++) {
                    int off = ni * 8 + 2 * (l & 3);
                    float v0 = acc[mi][ni][rr * 2 + 0] + bias[nb + off];
                    float v1 = acc[mi][ni][rr * 2 + 1] + bias[nb + off + 1];
                    *(float2*)(rowp + off) = make_float2(v0, v1);
                }
            }
        }
    }
}

// ---------------- MMA attention ----------------------------------------------
// One CTA per (b,h). S = Q K^T (HMMA, fp32 acc) + bias -> smem;
// softmax rows (in-place fp32->fp16); O = P V (HMMA) scaled by 1/sum.
__global__ __launch_bounds__(128) void attn_kernel() {
    extern __shared__ __align__(16) char smem[];
    const uint32_t sb = smem_u32(smem);
    const int tid = threadIdx.x;
    const int wid = tid >> 5, l = tid & 31;
    const int bh = blockIdx.x;
    const int h = bh & (NH - 1);
    const int b = bh >> 4;

    // ---- stage Q, K (98 rows), V (zero-padded to 112 rows), 80B row pitch ---
    const uint4* qg = (const uint4*)(g_q + (size_t)bh * Nn * HD);
    const uint4* kg = (const uint4*)(g_k + (size_t)bh * Nn * HD);
    const uint4* vg = (const uint4*)(g_v + (size_t)bh * Nn * HD);
    for (int t = tid; t < 392; t += 128) {          // 98 rows * 4 chunks
        int row = t >> 2, c = t & 3;
        sts128(sb + OQ  + row * 80 + c * 16, qg[t]);
        sts128(sb + OKs + row * 80 + c * 16, kg[t]);
    }
    for (int t = tid; t < 448; t += 128) {          // V: 112 rows, pad zeroed
        int row = t >> 2, c = t & 3;
        if (row < 98) sts128(sb + OV + row * 80 + c * 16, vg[t]);
        else          sts128(sb + OV + row * 80 + c * 16, make_uint4(0, 0, 0, 0));
    }
    __syncthreads();

    // ---- S = Q K^T : warp w owns m16-tiles {2w, 2w+1} (7 tiles total) -------
    float accS[2][13][4];
#pragma unroll
    for (int t = 0; t < 2; t++)
#pragma unroll
        for (int n = 0; n < 13; n++)
#pragma unroll
            for (int c = 0; c < 4; c++) accS[t][n][c] = 0.f;

#pragma unroll
    for (int ks = 0; ks < 2; ks++) {
        uint32_t aS[2][4];
#pragma unroll
        for (int t = 0; t < 2; t++) {
            int mt = wid * 2 + t;
            if (mt < 7) {
                uint32_t ad = sb + OQ + (uint32_t)(mt * 16 + (l & 15)) * 80
                            + (uint32_t)(ks * 2 + (l >> 4)) * 16;
                ldsm4(aS[t][0], aS[t][1], aS[t][2], aS[t][3], ad);
            }
        }
        uint32_t bS[13][2];
#pragma unroll
        for (int p = 0; p < 7; p++) {
            uint32_t bd = sb + OKs + (uint32_t)(p * 16 + (l >> 4) * 8 + (l & 7)) * 80
                        + (uint32_t)(ks * 2 + ((l >> 3) & 1)) * 16;
            uint32_t r0, r1, r2, r3;
            ldsm4(r0, r1, r2, r3, bd);
            bS[2*p][0] = r0; bS[2*p][1] = r1;
            if (2*p + 1 < 13) { bS[2*p+1][0] = r2; bS[2*p+1][1] = r3; }
        }
#pragma unroll
        for (int t = 0; t < 2; t++) {
            int mt = wid * 2 + t;
            if (mt < 7)
#pragma unroll
                for (int ni = 0; ni < 13; ni++)
                    mma4(accS[t][ni], aS[t], bS[ni]);
        }
    }

    // ---- S epilogue: + bias, store fp32 rows to smem ------------------------
    {
        const float* bpre = g_bias_pre + h * (Nn * Nn);
#pragma unroll
        for (int t = 0; t < 2; t++) {
            int mt = wid * 2 + t;
            if (mt >= 7) continue;
#pragma unroll
            for (int rr = 0; rr < 2; rr++) {
                int r = mt * 16 + (l >> 2) + rr * 8;
                if (r >= 98) continue;
                float* srow = (float*)(smem + OS + r * 416);
                const float* brow = bpre + r * 98;
#pragma unroll
                for (int ni = 0; ni < 13; ni++) {
                    int c = ni * 8 + 2 * (l & 3);
                    if (c < 97) {
                        float2 bb = *(const float2*)(brow + c);
                        srow[c]     = accS[t][ni][rr * 2 + 0] + bb.x;
                        srow[c + 1] = accS[t][ni][rr * 2 + 1] + bb.y;
                    }
                }
            }
        }
    }
    __syncthreads();

    // ---- softmax per row; in-place fp32 -> fp16 (forward-safe) --------------
    if (tid < 98) {
        float* row = (float*)(smem + OS + tid * 416);
        __half* rowh = (__half*)row;
        float m = -1e30f;
        for (int j = 0; j < 98; j++) m = fmaxf(m, row[j]);
        float sum = 0.f;
        for (int j = 0; j < 98; j++) {
            float e = __expf(row[j] - m);
            sum += e;
            rowh[j] = __float2half(e);
        }
#pragma unroll
        for (int j = 98; j < 112; j++) rowh[j] = __ushort_as_half(0);
        ((float*)(smem + OINV))[tid] = 1.f / sum;
    }
    __syncthreads();

    // ---- O = P V : k over 7 k16-steps; V via ldmatrix.trans -----------------
    float accO[2][4][4];
#pragma unroll
    for (int t = 0; t < 2; t++)
#pragma unroll
        for (int n = 0; n < 4; n++)
#pragma unroll
            for (int c = 0; c < 4; c++) accO[t][n][c] = 0.f;

#pragma unroll
    for (int kst = 0; kst < 7; kst++) {
        uint32_t aO[2][4];
#pragma unroll
        for (int t = 0; t < 2; t++) {
            int mt = wid * 2 + t;
            if (mt < 7) {
                uint32_t ad = sb + OS + (uint32_t)(mt * 16 + (l & 15)) * 416
                            + (uint32_t)(kst * 2 + (l >> 4)) * 16;
                ldsm4(aO[t][0], aO[t][1], aO[t][2], aO[t][3], ad);
            }
        }
        uint32_t bO[4][2];
#pragma unroll
        for (int half = 0; half < 2; half++) {
            uint32_t bd = sb + OV
                        + (uint32_t)(kst * 16 + (l & 7) + ((l >> 3) & 1) * 8) * 80
                        + (uint32_t)((l >> 4) * 8 + half * 16) * 2;
            uint32_t r0, r1, r2, r3;
            ldsm4t(r0, r1, r2, r3, bd);
            bO[2*half][0] = r0;   bO[2*half][1] = r1;
            bO[2*half+1][0] = r2; bO[2*half+1][1] = r3;
        }
#pragma unroll
        for (int t = 0; t < 2; t++) {
            int mt = wid * 2 + t;
            if (mt < 7)
#pragma unroll
                for (int ni = 0; ni < 4; ni++)
                    mma4(accO[t][ni], aO[t], bO[ni]);
        }
    }

    // ---- O epilogue: scale by 1/sum, write fp16 to g_ah ---------------------
#pragma unroll
    for (int t = 0; t < 2; t++) {
        int mt = wid * 2 + t;
        if (mt >= 7) continue;
#pragma unroll
        for (int rr = 0; rr < 2; rr++) {
            int r = mt * 16 + (l >> 2) + rr * 8;
            if (r >= 98) continue;
            float inv = ((float*)(smem + OINV))[r];
            __half* orow = g_ah + ((size_t)b * Nn + r) * DIM + h * HD;
#pragma unroll
            for (int ni = 0; ni < 4; ni++) {
                int c = ni * 8 + 2 * (l & 3);
                *(__half2*)(orow + c) =
                    __floats2half2_rn(accO[t][ni][rr * 2 + 0] * inv,
                                      accO[t][ni][rr * 2 + 1] * inv);
            }
        }
    }
}

// ---------------- launch -----------------------------------------------------
extern "C" void kernel_launch(void* const* d_in, const int* in_sizes, int n_in,
                              void* d_out, int out_size) {
    const float* x          = (const float*)d_in[0];
    const float* qkv_w      = (const float*)d_in[1];
    const float* qkv_b      = (const float*)d_in[2];
    const float* proj_w     = (const float*)d_in[3];
    const float* proj_b     = (const float*)d_in[4];
    const float* bias_table = (const float*)d_in[5];
    const int*   rel_index  = (const int*)d_in[6];
    float*       out        = (float*)d_out;

    static bool inited = false;
    if (!inited) {
        cudaFuncSetAttribute(gemm_kernel<true>,
                             cudaFuncAttributeMaxDynamicSharedMemorySize, SMEM_GEMM);
        cudaFuncSetAttribute(gemm_kernel<false>,
                             cudaFuncAttributeMaxDynamicSharedMemorySize, SMEM_GEMM);
        cudaFuncSetAttribute(attn_kernel,
                             cudaFuncAttributeMaxDynamicSharedMemorySize, SMEM_ATTN);
        inited = true;
    }

    conv_x_kernel<<<(int)((XELEMS / 4 + 255) / 256), 256>>>(x);
    prep_kernel<<<(PREP_TOT + 255) / 256, 256>>>(qkv_w, proj_w, bias_table, rel_index);
    gemm_kernel<true><<<dim3(QKV_N / 128, Mrows / 128), 256, SMEM_GEMM>>>(qkv_b, nullptr);
    attn_kernel<<<Bsz * NH, 128, SMEM_ATTN>>>();
    gemm_kernel<false><<<dim3(DIM / 128, Mrows / 128), 256, SMEM_GEMM>>>(proj_b, out);
}

// round 10
// speedup vs baseline: 2.2505x; 1.1005x over previous
#include <cuda_runtime.h>
#include <cuda_fp16.h>
#include <cstdint>

#define Bsz 512
#define Nn  98
#define DIM 512
#define NH  16
#define HD  32
#define Mrows (Bsz*Nn)
#define QKV_N (3*DIM)
#define SCALE 0.17677669529663687f
#define XELEMS ((size_t)Mrows*DIM)

#define KT 32
#define NSTAGE 4
#define TILE_B 10240
#define STAGE_B (2*TILE_B)
#define SMEM_GEMM (NSTAGE*STAGE_B)

#define W_QKV (QKV_N*DIM)
#define W_PROJ (DIM*DIM)
#define BIAS_T (NH*Nn*Nn)
#define PREP_TOT (W_QKV + W_PROJ + BIAS_T)

// attention smem layout (bytes)
#define OQ 0
#define OK2 8960
#define OV 17920
#define OP 26880                 // 112 rows x 224 B (fp16 P)
#define SMEM_ATTN (OP + 112*224) // 51968

// ---------------- scratch ----------------------------------------------------
__device__ __half g_q[(size_t)Bsz*NH*Nn*HD];
__device__ __half g_k[(size_t)Bsz*NH*Nn*HD];
__device__ __half g_v[(size_t)Bsz*NH*Nn*HD];
__device__ __half g_xh[XELEMS];
__device__ __half g_ah[XELEMS];
__device__ __half g_wqh[(size_t)QKV_N*DIM];
__device__ __half g_wph[(size_t)DIM*DIM];
__device__ float g_bias_pre[NH*Nn*Nn];

// ---------------- helpers ----------------------------------------------------
__device__ __forceinline__ uint32_t smem_u32(const void* p) {
    uint32_t a;
    asm("{ .reg .u64 t; cvta.to.shared.u64 t, %1; cvt.u32.u64 %0, t; }"
        : "=r"(a) : "l"(p));
    return a;
}
__device__ __forceinline__ void cp16(uint32_t s, const void* g) {
    asm volatile("cp.async.cg.shared.global [%0], [%1], 16;" :: "r"(s), "l"(g));
}
__device__ __forceinline__ void ldsm4(uint32_t& r0, uint32_t& r1, uint32_t& r2,
                                      uint32_t& r3, uint32_t a) {
    asm volatile("ldmatrix.sync.aligned.m8n8.x4.shared.b16 {%0,%1,%2,%3}, [%4];"
                 : "=r"(r0), "=r"(r1), "=r"(r2), "=r"(r3) : "r"(a));
}
__device__ __forceinline__ void ldsm4t(uint32_t& r0, uint32_t& r1, uint32_t& r2,
                                       uint32_t& r3, uint32_t a) {
    asm volatile("ldmatrix.sync.aligned.m8n8.x4.trans.shared.b16 {%0,%1,%2,%3}, [%4];"
                 : "=r"(r0), "=r"(r1), "=r"(r2), "=r"(r3) : "r"(a));
}
__device__ __forceinline__ void sts128(uint32_t a, uint4 v) {
    asm volatile("st.shared.v4.b32 [%0], {%1,%2,%3,%4};"
                 :: "r"(a), "r"(v.x), "r"(v.y), "r"(v.z), "r"(v.w) : "memory");
}
__device__ __forceinline__ void mma4(float* d, const uint32_t* a, const uint32_t* b) {
    asm volatile("mma.sync.aligned.m16n8k16.row.col.f32.f16.f16.f32 "
                 "{%0,%1,%2,%3}, {%4,%5,%6,%7}, {%8,%9}, {%0,%1,%2,%3};"
                 : "+f"(d[0]), "+f"(d[1]), "+f"(d[2]), "+f"(d[3])
                 : "r"(a[0]), "r"(a[1]), "r"(a[2]), "r"(a[3]), "r"(b[0]), "r"(b[1]));
}
__device__ __forceinline__ uint32_t packh2(__half a, __half b) {
    __half2 t = __halves2half2(a, b);
    return reinterpret_cast<uint32_t&>(t);
}

// ---------------- conversion / prep kernels ---------------------------------
__global__ __launch_bounds__(256) void conv_x_kernel(const float* __restrict__ x) {
    size_t i = (size_t)blockIdx.x * 256 + threadIdx.x;
    if (i >= XELEMS / 4) return;
    float4 v = ((const float4*)x)[i];
    ((uint2*)g_xh)[i] = make_uint2(
        packh2(__float2half(v.x), __float2half(v.y)),
        packh2(__float2half(v.z), __float2half(v.w)));
}

__global__ __launch_bounds__(256) void prep_kernel(const float* __restrict__ wq,
                                                   const float* __restrict__ wp,
                                                   const float* __restrict__ bt,
                                                   const int* __restrict__ ri) {
    int idx = blockIdx.x * 256 + threadIdx.x;
    if (idx < W_QKV) {
        int n = idx >> 9, k = idx & 511;
        g_wqh[idx] = __float2half(wq[(size_t)k * QKV_N + n]);
    } else if (idx < W_QKV + W_PROJ) {
        int i2 = idx - W_QKV;
        int n = i2 >> 9, k = i2 & 511;
        g_wph[i2] = __float2half(wp[(size_t)k * DIM + n]);
    } else if (idx < PREP_TOT) {
        int i2 = idx - W_QKV - W_PROJ;
        int h = i2 / (Nn * Nn);
        int t = i2 - h * (Nn * Nn);
        g_bias_pre[i2] = bt[ri[t] * NH + h];
    }
}

// ---------------- HMMA GEMM (unchanged) --------------------------------------
template<bool IS_QKV>
__global__ __launch_bounds__(256) void gemm_kernel(const float* __restrict__ bias,
                                                   float* __restrict__ outp) {
    extern __shared__ __align__(16) char smraw[];
    const uint32_t sbase = smem_u32(smraw);
    const int tid = threadIdx.x;
    const int wid = tid >> 5, l = tid & 31;
    const int bm = blockIdx.y * 128, bn = blockIdx.x * 128;
    const int wm = wid & 1, wn = wid >> 1;

    const __half* __restrict__ Ah = IS_QKV ? g_xh : g_ah;
    const __half* __restrict__ Bh = IS_QKV ? g_wqh : g_wph;

    auto issue = [&](int st, int kt) {
        const int k0 = kt * KT;
        const uint32_t base = sbase + st * STAGE_B;
        const int c = tid & 3;
#pragma unroll
        for (int i = 0; i < 2; i++) {
            const int row = (i * 256 + tid) >> 2;
            cp16(base + row * 80 + c * 16,
                 Ah + (size_t)(bm + row) * 512 + k0 + c * 8);
            cp16(base + TILE_B + row * 80 + c * 16,
                 Bh + (size_t)(bn + row) * 512 + k0 + c * 8);
        }
        asm volatile("cp.async.commit_group;" ::: "memory");
    };

    float acc[4][4][4];
#pragma unroll
    for (int a = 0; a < 4; a++)
#pragma unroll
        for (int b = 0; b < 4; b++)
#pragma unroll
            for (int c = 0; c < 4; c++) acc[a][b][c] = 0.f;

    issue(0, 0);
    issue(1, 1);
    issue(2, 2);

    for (int kt = 0; kt < 16; kt++) {
        if (kt <= 13)      asm volatile("cp.async.wait_group 2;" ::: "memory");
        else if (kt == 14) asm volatile("cp.async.wait_group 1;" ::: "memory");
        else               asm volatile("cp.async.wait_group 0;" ::: "memory");
        __syncthreads();
        if (kt + 3 < 16) issue((kt + 3) % NSTAGE, kt + 3);

        const uint32_t base = sbase + (kt % NSTAGE) * STAGE_B;
#pragma unroll
        for (int ks = 0; ks < 2; ks++) {
            uint32_t af[4][4], bf[4][2];
#pragma unroll
            for (int mi = 0; mi < 4; mi++) {
                uint32_t ad = base + (uint32_t)(wm * 64 + mi * 16 + (l & 15)) * 80
                            + (uint32_t)(ks * 2 + (l >> 4)) * 16;
                ldsm4(af[mi][0], af[mi][1], af[mi][2], af[mi][3], ad);
            }
#pragma unroll
            for (int p = 0; p < 2; p++) {
                uint32_t nrow = (uint32_t)(wn * 32 + p * 16 + (l >> 4) * 8 + (l & 7));
                uint32_t ck   = (uint32_t)(ks * 2 + ((l >> 3) & 1));
                uint32_t bd = base + TILE_B + nrow * 80 + ck * 16;
                uint32_t r0, r1, r2, r3;
                ldsm4(r0, r1, r2, r3, bd);
                bf[2*p][0] = r0; bf[2*p][1] = r1; bf[2*p+1][0] = r2; bf[2*p+1][1] = r3;
            }
#pragma unroll
            for (int mi = 0; mi < 4; mi++)
#pragma unroll
                for (int ni = 0; ni < 4; ni++)
                    mma4(acc[mi][ni], af[mi], bf[ni]);
        }
    }

    if (IS_QKV) {
        const int which = bn >> 9;
        const int h = ((bn >> 5) + wn) & (NH - 1);
        __half* dst0 = which == 0 ? g_q : which == 1 ? g_k : g_v;
        const float sc = which == 0 ? SCALE : 1.f;
        const float* bptr = bias + which * 512 + h * 32;
#pragma unroll
        for (int mi = 0; mi < 4; mi++) {
#pragma unroll
            for (int rr = 0; rr < 2; rr++) {
                int m = bm + wm * 64 + mi * 16 + (l >> 2) + rr * 8;
                int b = m / Nn, r = m - b * Nn;
                __half* rowp = dst0 + ((size_t)(b * NH + h) * Nn + r) * HD;
#pragma unroll
                for (int ni = 0; ni < 4; ni++) {
                    int hd = ni * 8 + 2 * (l & 3);
                    float v0 = (acc[mi][ni][rr * 2 + 0] + bptr[hd])     * sc;
                    float v1 = (acc[mi][ni][rr * 2 + 1] + bptr[hd + 1]) * sc;
                    *(__half2*)(rowp + hd) = __floats2half2_rn(v0, v1);
                }
            }
        }
    } else {
        const int nb = bn + wn * 32;
#pragma unroll
        for (int mi = 0; mi < 4; mi++) {
#pragma unroll
            for (int rr = 0; rr < 2; rr++) {
                int m = bm + wm * 64 + mi * 16 + (l >> 2) + rr * 8;
                float* rowp = outp + (size_t)m * DIM + nb;
#pragma unroll
                for (int ni = 0; ni < 4; ni++) {
                    int off = ni * 8 + 2 * (l & 3);
                    float v0 = acc[mi][ni][rr * 2 + 0] + bias[nb + off];
                    float v1 = acc[mi][ni][rr * 2 + 1] + bias[nb + off + 1];
                    *(float2*)(rowp + off) = make_float2(v0, v1);
                }
            }
        }
    }
}

// ---------------- MMA attention with register-resident softmax ---------------
__global__ __launch_bounds__(128) void attn_kernel() {
    extern __shared__ __align__(16) char smem[];
    const uint32_t sb = smem_u32(smem);
    const int tid = threadIdx.x;
    const int wid = tid >> 5, l = tid & 31;
    const int bh = blockIdx.x;
    const int h = bh & (NH - 1);
    const int b = bh >> 4;

    // ---- stage Q, K (98 rows), V (zero-padded to 112), zero P pad cols ------
    const uint4* qg = (const uint4*)(g_q + (size_t)bh * Nn * HD);
    const uint4* kg = (const uint4*)(g_k + (size_t)bh * Nn * HD);
    const uint4* vg = (const uint4*)(g_v + (size_t)bh * Nn * HD);
    for (int t = tid; t < 392; t += 128) {
        int row = t >> 2, c = t & 3;
        sts128(sb + OQ  + row * 80 + c * 16, qg[t]);
        sts128(sb + OK2 + row * 80 + c * 16, kg[t]);
    }
    for (int t = tid; t < 448; t += 128) {
        int row = t >> 2, c = t & 3;
        if (row < 98) sts128(sb + OV + row * 80 + c * 16, vg[t]);
        else          sts128(sb + OV + row * 80 + c * 16, make_uint4(0, 0, 0, 0));
    }
    for (int r = tid; r < 112; r += 128)     // P cols 104-111 (bytes 208-223)
        sts128(sb + OP + r * 224 + 208, make_uint4(0, 0, 0, 0));
    __syncthreads();

    // ---- S = Q K^T ----------------------------------------------------------
    float accS[2][13][4];
#pragma unroll
    for (int t = 0; t < 2; t++)
#pragma unroll
        for (int n = 0; n < 13; n++)
#pragma unroll
            for (int c = 0; c < 4; c++) accS[t][n][c] = 0.f;

#pragma unroll
    for (int ks = 0; ks < 2; ks++) {
        uint32_t aS[2][4];
#pragma unroll
        for (int t = 0; t < 2; t++) {
            int mt = wid * 2 + t;
            if (mt < 7) {
                uint32_t ad = sb + OQ + (uint32_t)(mt * 16 + (l & 15)) * 80
                            + (uint32_t)(ks * 2 + (l >> 4)) * 16;
                ldsm4(aS[t][0], aS[t][1], aS[t][2], aS[t][3], ad);
            }
        }
        uint32_t bS[13][2];
#pragma unroll
        for (int p = 0; p < 7; p++) {
            uint32_t bd = sb + OK2 + (uint32_t)(p * 16 + (l >> 4) * 8 + (l & 7)) * 80
                        + (uint32_t)(ks * 2 + ((l >> 3) & 1)) * 16;
            uint32_t r0, r1, r2, r3;
            ldsm4(r0, r1, r2, r3, bd);
            bS[2*p][0] = r0; bS[2*p][1] = r1;
            if (2*p + 1 < 13) { bS[2*p+1][0] = r2; bS[2*p+1][1] = r3; }
        }
#pragma unroll
        for (int t = 0; t < 2; t++) {
            int mt = wid * 2 + t;
            if (mt < 7)
#pragma unroll
                for (int ni = 0; ni < 13; ni++)
                    mma4(accS[t][ni], aS[t], bS[ni]);
        }
    }

    // ---- register softmax: bias add, quad-shfl max/sum, fp16 P store --------
    const float* bpre = g_bias_pre + h * (Nn * Nn);
    float invv[2][2];
#pragma unroll
    for (int t = 0; t < 2; t++) {
        int mt = wid * 2 + t;
        if (mt >= 7) continue;                 // warp-uniform (only wid==3,t==1)
#pragma unroll
        for (int rr = 0; rr < 2; rr++) {
            int r = mt * 16 + (l >> 2) + rr * 8;
            float mx = -1e30f;
#pragma unroll
            for (int ni = 0; ni < 13; ni++) {
                int c = ni * 8 + 2 * (l & 3);
                float b0 = 0.f, b1 = 0.f;
                if (r < 98 && c < 98) {
                    float2 bb = *(const float2*)(bpre + r * 98 + c);
                    b0 = bb.x; b1 = bb.y;
                }
                float s0 = accS[t][ni][rr * 2 + 0] + b0;
                float s1 = accS[t][ni][rr * 2 + 1] + b1;
                accS[t][ni][rr * 2 + 0] = s0;
                accS[t][ni][rr * 2 + 1] = s1;
                if (c < 98) mx = fmaxf(mx, fmaxf(s0, s1));
            }
            mx = fmaxf(mx, __shfl_xor_sync(0xFFFFFFFF, mx, 1));
            mx = fmaxf(mx, __shfl_xor_sync(0xFFFFFFFF, mx, 2));
            float sum = 0.f;
#pragma unroll
            for (int ni = 0; ni < 13; ni++) {
                int c = ni * 8 + 2 * (l & 3);
                float e0 = 0.f, e1 = 0.f;
                if (c < 98) {
                    e0 = __expf(accS[t][ni][rr * 2 + 0] - mx);
                    e1 = __expf(accS[t][ni][rr * 2 + 1] - mx);
                }
                sum += e0 + e1;
                uint32_t pk = packh2(__float2half(e0), __float2half(e1));
                asm volatile("st.shared.b32 [%0], %1;"
                             :: "r"(sb + OP + (uint32_t)(r * 224 + c * 2)), "r"(pk)
                             : "memory");
            }
            sum += __shfl_xor_sync(0xFFFFFFFF, sum, 1);
            sum += __shfl_xor_sync(0xFFFFFFFF, sum, 2);
            invv[t][rr] = 1.f / sum;
        }
    }
    __syncthreads();

    // ---- O = P V ------------------------------------------------------------
    float accO[2][4][4];
#pragma unroll
    for (int t = 0; t < 2; t++)
#pragma unroll
        for (int n = 0; n < 4; n++)
#pragma unroll
            for (int c = 0; c < 4; c++) accO[t][n][c] = 0.f;

#pragma unroll
    for (int kst = 0; kst < 7; kst++) {
        uint32_t aO[2][4];
#pragma unroll
        for (int t = 0; t < 2; t++) {
            int mt = wid * 2 + t;
            if (mt < 7) {
                uint32_t ad = sb + OP + (uint32_t)(mt * 16 + (l & 15)) * 224
                            + (uint32_t)(kst * 2 + (l >> 4)) * 16;
                ldsm4(aO[t][0], aO[t][1], aO[t][2], aO[t][3], ad);
            }
        }
        uint32_t bO[4][2];
#pragma unroll
        for (int half = 0; half < 2; half++) {
            uint32_t bd = sb + OV
                        + (uint32_t)(kst * 16 + (l & 7) + ((l >> 3) & 1) * 8) * 80
                        + (uint32_t)((l >> 4) * 8 + half * 16) * 2;
            uint32_t r0, r1, r2, r3;
            ldsm4t(r0, r1, r2, r3, bd);
            bO[2*half][0] = r0;   bO[2*half][1] = r1;
            bO[2*half+1][0] = r2; bO[2*half+1][1] = r3;
        }
#pragma unroll
        for (int t = 0; t < 2; t++) {
            int mt = wid * 2 + t;
            if (mt < 7)
#pragma unroll
                for (int ni = 0; ni < 4; ni++)
                    mma4(accO[t][ni], aO[t], bO[ni]);
        }
    }

    // ---- O epilogue: scale by register inv, write fp16 ----------------------
#pragma unroll
    for (int t = 0; t < 2; t++) {
        int mt = wid * 2 + t;
        if (mt >= 7) continue;
#pragma unroll
        for (int rr = 0; rr < 2; rr++) {
            int r = mt * 16 + (l >> 2) + rr * 8;
            if (r >= 98) continue;
            float inv = invv[t][rr];
            __half* orow = g_ah + ((size_t)b * Nn + r) * DIM + h * HD;
#pragma unroll
            for (int ni = 0; ni < 4; ni++) {
                int c = ni * 8 + 2 * (l & 3);
                *(__half2*)(orow + c) =
                    __floats2half2_rn(accO[t][ni][rr * 2 + 0] * inv,
                                      accO[t][ni][rr * 2 + 1] * inv);
            }
        }
    }
}

// ---------------- launch -----------------------------------------------------
extern "C" void kernel_launch(void* const* d_in, const int* in_sizes, int n_in,
                              void* d_out, int out_size) {
    const float* x          = (const float*)d_in[0];
    const float* qkv_w      = (const float*)d_in[1];
    const float* qkv_b      = (const float*)d_in[2];
    const float* proj_w     = (const float*)d_in[3];
    const float* proj_b     = (const float*)d_in[4];
    const float* bias_table = (const float*)d_in[5];
    const int*   rel_index  = (const int*)d_in[6];
    float*       out        = (float*)d_out;

    static bool inited = false;
    if (!inited) {
        cudaFuncSetAttribute(gemm_kernel<true>,
                             cudaFuncAttributeMaxDynamicSharedMemorySize, SMEM_GEMM);
        cudaFuncSetAttribute(gemm_kernel<false>,
                             cudaFuncAttributeMaxDynamicSharedMemorySize, SMEM_GEMM);
        cudaFuncSetAttribute(attn_kernel,
                             cudaFuncAttributeMaxDynamicSharedMemorySize, SMEM_ATTN);
        inited = true;
    }

    conv_x_kernel<<<(int)((XELEMS / 4 + 255) / 256), 256>>>(x);
    prep_kernel<<<(PREP_TOT + 255) / 256, 256>>>(qkv_w, proj_w, bias_table, rel_index);
    gemm_kernel<true><<<dim3(QKV_N / 128, Mrows / 128), 256, SMEM_GEMM>>>(qkv_b, nullptr);
    attn_kernel<<<Bsz * NH, 128, SMEM_ATTN>>>();
    gemm_kernel<false><<<dim3(DIM / 128, Mrows / 128), 256, SMEM_GEMM>>>(proj_b, out);
}